// round 9
// baseline (speedup 1.0000x reference)
#include <cuda_runtime.h>
#include <cuda_bf16.h>
#include <math.h>
#include <stdint.h>
#include <string.h>

typedef unsigned int u32;

// ---------------- problem constants ----------------
constexpr int BS  = 8;
constexpr int C   = 128;
constexpr int HH  = 128;
constexpr int WW  = 128;
constexpr int P   = HH * WW;
constexpr long long M = (long long)BS * P;  // 131072 rows
constexpr int HID = 512;

// ---------------- device scratch ----------------
__device__ float          g_xt  [(size_t)M * C];       // residual stream (fp32)
__device__ __nv_bfloat16  g_qkvb[(size_t)M * 3 * C];   // qkv (bf16)
__device__ __nv_bfloat16  g_abuf[(size_t)M * C];       // attention out (bf16)
__device__ float          g_xt2 [(size_t)M * C];       // residual after attn (fp32)
__device__ __nv_bfloat16  g_h   [(size_t)M * HID];     // gelu(fc1) (bf16)

// transposed bf16 weights [N][K]
__device__ __nv_bfloat16  g_wqkv_t[384 * 128];
__device__ __nv_bfloat16  g_proj_t[128 * 128];
__device__ __nv_bfloat16  g_fc1_t [512 * 128];
__device__ __nv_bfloat16  g_fc2_t [128 * 512];

// =================================================================
// mma / ldmatrix primitives
// =================================================================
__device__ __forceinline__ void ldsm_x4(u32 &r0, u32 &r1, u32 &r2, u32 &r3, u32 addr)
{
    asm volatile("ldmatrix.sync.aligned.m8n8.x4.shared.b16 {%0,%1,%2,%3}, [%4];"
                 : "=r"(r0), "=r"(r1), "=r"(r2), "=r"(r3) : "r"(addr));
}
__device__ __forceinline__ void ldsm_x4_t(u32 &r0, u32 &r1, u32 &r2, u32 &r3, u32 addr)
{
    asm volatile("ldmatrix.sync.aligned.m8n8.x4.trans.shared.b16 {%0,%1,%2,%3}, [%4];"
                 : "=r"(r0), "=r"(r1), "=r"(r2), "=r"(r3) : "r"(addr));
}
__device__ __forceinline__ void mma_bf16(float* d, const u32* a, const u32* b)
{
    asm volatile("mma.sync.aligned.m16n8k16.row.col.f32.bf16.bf16.f32 "
                 "{%0,%1,%2,%3}, {%4,%5,%6,%7}, {%8,%9}, {%0,%1,%2,%3};"
                 : "+f"(d[0]), "+f"(d[1]), "+f"(d[2]), "+f"(d[3])
                 : "r"(a[0]), "r"(a[1]), "r"(a[2]), "r"(a[3]),
                   "r"(b[0]), "r"(b[1]));
}
__device__ __forceinline__ u32 pack_bf16x2(float a, float b)
{
    __nv_bfloat162 t = __floats2bfloat162_rn(a, b);
    u32 r;
    memcpy(&r, &t, 4);
    return r;
}

// =================================================================
// merged weight transpose + bf16 convert (all 4 weights, one launch)
// =================================================================
__global__ void wt_all_kernel(const float* __restrict__ wqkv, const float* __restrict__ projw,
                              const float* __restrict__ fc1w, const float* __restrict__ fc2w,
                              __nv_bfloat16* oq, __nv_bfloat16* op,
                              __nv_bfloat16* o1, __nv_bfloat16* o2)
{
    __shared__ float t[32][33];
    int id = blockIdx.x;
    const float* W; __nv_bfloat16* Wt; int K, N, local;
    if (id < 48)       { W = wqkv;  Wt = oq; K = 128; N = 384; local = id; }
    else if (id < 64)  { W = projw; Wt = op; K = 128; N = 128; local = id - 48; }
    else if (id < 128) { W = fc1w;  Wt = o1; K = 128; N = 512; local = id - 64; }
    else               { W = fc2w;  Wt = o2; K = 512; N = 128; local = id - 128; }
    int nTiles = N / 32;
    int n0 = (local % nTiles) * 32;
    int k0 = (local / nTiles) * 32;
    int tx = threadIdx.x, ty = threadIdx.y;
    for (int i = ty; i < 32; i += 8)
        t[i][tx] = W[(size_t)(k0 + i) * N + n0 + tx];
    __syncthreads();
    for (int i = ty; i < 32; i += 8)
        Wt[(size_t)(n0 + i) * K + k0 + tx] = __float2bfloat16(t[tx][i]);
}

// =================================================================
// Kernel 1: depthwise 3x3 conv + bias + residual -> xt (B,P,C) fp32
// =================================================================
__global__ __launch_bounds__(256) void conv_kernel(
    const float* __restrict__ x, const float* __restrict__ cw,
    const float* __restrict__ cb, float* __restrict__ xt)
{
    int b  = blockIdx.z;
    int h  = blockIdx.y;
    int c0 = (blockIdx.x >> 2) * 32;
    int w0 = (blockIdx.x & 3) * 32;
    __shared__ float sx[32][3][36];
    __shared__ float so[32][33];
    int tid = threadIdx.x;

    for (int i = tid; i < 32 * 3 * 34; i += 256) {
        int c  = i / (3 * 34);
        int r  = (i / 34) % 3;
        int wi = i % 34;
        int hh = h + r - 1;
        int wg = w0 + wi - 1;
        float v = 0.f;
        if (hh >= 0 && hh < HH && wg >= 0 && wg < WW)
            v = x[(((size_t)b * C + c0 + c) * HH + hh) * WW + wg];
        sx[c][r][wi] = v;
    }
    __syncthreads();

    int c     = tid >> 3;
    int wbase = (tid & 7) * 4;
    const float* wg9 = cw + (size_t)(c0 + c) * 9;
    float w00 = wg9[0], w01 = wg9[1], w02 = wg9[2];
    float w10 = wg9[3], w11 = wg9[4], w12 = wg9[5];
    float w20 = wg9[6], w21 = wg9[7], w22 = wg9[8];
    float bias = cb[c0 + c];
#pragma unroll
    for (int j = 0; j < 4; j++) {
        int wi = wbase + j;
        float acc = sx[c][0][wi] * w00 + sx[c][0][wi+1] * w01 + sx[c][0][wi+2] * w02
                  + sx[c][1][wi] * w10 + sx[c][1][wi+1] * w11 + sx[c][1][wi+2] * w12
                  + sx[c][2][wi] * w20 + sx[c][2][wi+1] * w21 + sx[c][2][wi+2] * w22;
        so[c][wi] = acc + bias + sx[c][1][wi+1];
    }
    __syncthreads();

    int cc = tid & 31;
    for (int wr = tid >> 5; wr < 32; wr += 8) {
        xt[((size_t)b * P + (size_t)h * WW + w0 + wr) * C + c0 + cc] = so[cc][wr];
    }
}

// =================================================================
// Epilogue functors
// =================================================================
struct EpiQKVb {   // qkv -> bf16
    __nv_bfloat16* out;
    __device__ __forceinline__ void store(size_t row, int col, float2 v) const {
        *(__nv_bfloat162*)(out + row * 384 + col) = __floats2bfloat162_rn(v.x, v.y);
    }
};
struct EpiProj {   // xt2 = xt + ls1 * (v + bias)   (fp32 out)
    const float* bias; const float* ls; const float* resid; float* out;
    __device__ __forceinline__ void store(size_t row, int col, float2 v) const {
        float2 bb = *(const float2*)(bias + col);
        float2 ss = *(const float2*)(ls + col);
        float2 rr = *(const float2*)(resid + row * 128 + col);
        float2 o;
        o.x = rr.x + ss.x * (v.x + bb.x);
        o.y = rr.y + ss.y * (v.y + bb.y);
        *(float2*)(out + row * 128 + col) = o;
    }
};
struct EpiGelu {   // h = gelu(v + bias)  -> bf16, N=512
    const float* bias; __nv_bfloat16* out;
    __device__ __forceinline__ float gelu(float g) const {
        return 0.5f * g * (1.f + erff(g * 0.70710678118654752f));
    }
    __device__ __forceinline__ void store(size_t row, int col, float2 v) const {
        float2 bb = *(const float2*)(bias + col);
        *(__nv_bfloat162*)(out + row * 512 + col) =
            __floats2bfloat162_rn(gelu(v.x + bb.x), gelu(v.y + bb.y));
    }
};

// =================================================================
// Fused LayerNorm + bf16 GEMM (K=128): A fp32 -> LN -> resident As,
// B streamed in BK=32 stages. CTA 128xBN(128), 8 warps.
// =================================================================
constexpr int ASTR = 136;   // resident A row stride (17*16B -> ldsm conflict-free)
constexpr int LDS_S = 40;   // streamed tile row stride (5*16B)

template <class Epi>
__global__ __launch_bounds__(256, 2) void lngemm_kernel(
    const float* __restrict__ A, const float* __restrict__ lnw,
    const float* __restrict__ lnb, const __nv_bfloat16* __restrict__ Bw,
    Epi epi)
{
    __shared__ __nv_bfloat16 As[128][ASTR];
    __shared__ __nv_bfloat16 Bs[128][LDS_S];
    int tid = threadIdx.x, lane = tid & 31, w = tid >> 5;
    int wm = w & 1, wn = w >> 1;
    size_t rowBase = (size_t)blockIdx.y * 128;
    int    colBase = blockIdx.x * 128;

    // ---- LN stage: 2 threads per row ----
    {
        int row = tid >> 1, half = tid & 1;
        const float4* src = (const float4*)(A + (rowBase + row) * 128 + half * 64);
        float s = 0.f, q = 0.f;
#pragma unroll
        for (int i = 0; i < 16; i++) {
            float4 v = src[i];
            s += v.x + v.y + v.z + v.w;
            q += v.x*v.x + v.y*v.y + v.z*v.z + v.w*v.w;
        }
        s += __shfl_xor_sync(0xffffffffu, s, 1);
        q += __shfl_xor_sync(0xffffffffu, q, 1);
        float mean = s * (1.f / 128.f);
        float var  = q * (1.f / 128.f) - mean * mean;
        float rstd = rsqrtf(var + 1e-5f);
        const float4* wp = (const float4*)(lnw + half * 64);
        const float4* bp = (const float4*)(lnb + half * 64);
#pragma unroll
        for (int j = 0; j < 8; j++) {
            float4 a  = src[2*j],  b2  = src[2*j+1];
            float4 w4 = wp[2*j],   w42 = wp[2*j+1];
            float4 b4 = bp[2*j],   b42 = bp[2*j+1];
            u32 o[4];
            o[0] = pack_bf16x2((a.x-mean)*rstd*w4.x + b4.x,  (a.y-mean)*rstd*w4.y + b4.y);
            o[1] = pack_bf16x2((a.z-mean)*rstd*w4.z + b4.z,  (a.w-mean)*rstd*w4.w + b4.w);
            o[2] = pack_bf16x2((b2.x-mean)*rstd*w42.x + b42.x,(b2.y-mean)*rstd*w42.y + b42.y);
            o[3] = pack_bf16x2((b2.z-mean)*rstd*w42.z + b42.z,(b2.w-mean)*rstd*w42.w + b42.w);
            *(uint4*)&As[row][half * 64 + j * 8] = *(uint4*)o;
        }
    }

    // ---- mainloop: B streamed ----
    int ldRow = tid >> 1, ldCol = (tid & 1) * 16;
    const __nv_bfloat16* Bp = Bw + (size_t)(colBase + ldRow) * 128 + ldCol;
    uint4 bv0 = *(const uint4*)Bp, bv1 = *(const uint4*)(Bp + 8);

    float acc[4][4][4];
#pragma unroll
    for (int i = 0; i < 4; i++)
#pragma unroll
        for (int j = 0; j < 4; j++)
#pragma unroll
            for (int r = 0; r < 4; r++) acc[i][j][r] = 0.f;

    u32 sA = (u32)__cvta_generic_to_shared(&As[0][0]);
    u32 sB = (u32)__cvta_generic_to_shared(&Bs[0][0]);
    int arow = wm * 64 + (lane & 15);
    int brow = wn * 32 + (lane & 15);
    int csel = (lane >> 4) * 8;

#pragma unroll
    for (int s = 0; s < 4; s++) {
        __syncthreads();
        *(uint4*)&Bs[ldRow][ldCol]     = bv0;
        *(uint4*)&Bs[ldRow][ldCol + 8] = bv1;
        if (s < 3) {
            Bp += 32;
            bv0 = *(const uint4*)Bp; bv1 = *(const uint4*)(Bp + 8);
        }
        __syncthreads();
#pragma unroll
        for (int kk2 = 0; kk2 < 2; kk2++) {
            int acol = s * 32 + kk2 * 16 + csel;
            int bcol = kk2 * 16 + csel;
            u32 af[4][4], bf[4][2];
#pragma unroll
            for (int mi = 0; mi < 4; mi++) {
                u32 addr = sA + (u32)(((arow + mi * 16) * ASTR + acol) * 2);
                ldsm_x4(af[mi][0], af[mi][1], af[mi][2], af[mi][3], addr);
            }
#pragma unroll
            for (int np = 0; np < 2; np++) {
                u32 r0, r1, r2, r3;
                u32 addr = sB + (u32)(((brow + np * 16) * LDS_S + bcol) * 2);
                ldsm_x4(r0, r1, r2, r3, addr);
                bf[np * 2][0]     = r0; bf[np * 2][1]     = r2;
                bf[np * 2 + 1][0] = r1; bf[np * 2 + 1][1] = r3;
            }
#pragma unroll
            for (int mi = 0; mi < 4; mi++)
#pragma unroll
                for (int nj = 0; nj < 4; nj++)
                    mma_bf16(acc[mi][nj], af[mi], bf[nj]);
        }
    }

#pragma unroll
    for (int mi = 0; mi < 4; mi++)
#pragma unroll
        for (int rp = 0; rp < 2; rp++) {
            size_t r = rowBase + wm * 64 + mi * 16 + rp * 8 + (lane >> 2);
#pragma unroll
            for (int nj = 0; nj < 4; nj++) {
                int cgl = colBase + wn * 32 + nj * 8 + (lane & 3) * 2;
                epi.store(r, cgl, make_float2(acc[mi][nj][rp * 2],
                                              acc[mi][nj][rp * 2 + 1]));
            }
        }
}

// =================================================================
// bf16 GEMM (A,B streamed) with functor epilogue — used for proj
// =================================================================
template <class Epi>
__global__ __launch_bounds__(256, 2) void bgemm_kernel(
    const __nv_bfloat16* __restrict__ A, const __nv_bfloat16* __restrict__ Bw,
    int K, Epi epi)
{
    __shared__ __nv_bfloat16 As[128][LDS_S];
    __shared__ __nv_bfloat16 Bs[128][LDS_S];
    int tid = threadIdx.x, lane = tid & 31, w = tid >> 5;
    int wm = w & 1, wn = w >> 1;
    size_t rowBase = (size_t)blockIdx.y * 128;
    int    colBase = blockIdx.x * 128;

    int ldRow = tid >> 1;
    int ldCol = (tid & 1) * 16;
    const __nv_bfloat16* Ap = A  + (rowBase + ldRow) * K + ldCol;
    const __nv_bfloat16* Bp = Bw + (size_t)(colBase + ldRow) * K + ldCol;

    float acc[4][4][4];
#pragma unroll
    for (int i = 0; i < 4; i++)
#pragma unroll
        for (int j = 0; j < 4; j++)
#pragma unroll
            for (int r = 0; r < 4; r++) acc[i][j][r] = 0.f;

    uint4 av0 = *(const uint4*)Ap, av1 = *(const uint4*)(Ap + 8);
    uint4 bv0 = *(const uint4*)Bp, bv1 = *(const uint4*)(Bp + 8);

    u32 sA = (u32)__cvta_generic_to_shared(&As[0][0]);
    u32 sB = (u32)__cvta_generic_to_shared(&Bs[0][0]);
    int arow = wm * 64 + (lane & 15);
    int brow = wn * 32 + (lane & 15);
    int csel = (lane >> 4) * 8;

    for (int kt = 0; kt < K; kt += 32) {
        __syncthreads();
        *(uint4*)&As[ldRow][ldCol]     = av0;
        *(uint4*)&As[ldRow][ldCol + 8] = av1;
        *(uint4*)&Bs[ldRow][ldCol]     = bv0;
        *(uint4*)&Bs[ldRow][ldCol + 8] = bv1;
        if (kt + 32 < K) {
            Ap += 32; Bp += 32;
            av0 = *(const uint4*)Ap; av1 = *(const uint4*)(Ap + 8);
            bv0 = *(const uint4*)Bp; bv1 = *(const uint4*)(Bp + 8);
        }
        __syncthreads();
#pragma unroll
        for (int kk = 0; kk < 32; kk += 16) {
            u32 af[4][4], bf[4][2];
            int acol = kk + csel;
#pragma unroll
            for (int mi = 0; mi < 4; mi++) {
                u32 addr = sA + (u32)(((arow + mi * 16) * LDS_S + acol) * 2);
                ldsm_x4(af[mi][0], af[mi][1], af[mi][2], af[mi][3], addr);
            }
#pragma unroll
            for (int np = 0; np < 2; np++) {
                u32 r0, r1, r2, r3;
                u32 addr = sB + (u32)(((brow + np * 16) * LDS_S + acol) * 2);
                ldsm_x4(r0, r1, r2, r3, addr);
                bf[np * 2][0]     = r0; bf[np * 2][1]     = r2;
                bf[np * 2 + 1][0] = r1; bf[np * 2 + 1][1] = r3;
            }
#pragma unroll
            for (int mi = 0; mi < 4; mi++)
#pragma unroll
                for (int nj = 0; nj < 4; nj++)
                    mma_bf16(acc[mi][nj], af[mi], bf[nj]);
        }
    }

#pragma unroll
    for (int mi = 0; mi < 4; mi++)
#pragma unroll
        for (int rp = 0; rp < 2; rp++) {
            size_t r = rowBase + wm * 64 + mi * 16 + rp * 8 + (lane >> 2);
#pragma unroll
            for (int nj = 0; nj < 4; nj++) {
                int cgl = colBase + wn * 32 + nj * 8 + (lane & 3) * 2;
                epi.store(r, cgl, make_float2(acc[mi][nj][rp * 2],
                                              acc[mi][nj][rp * 2 + 1]));
            }
        }
}

// =================================================================
// FC2 GEMM (K=512) + bias + ls2 + residual + TRANSPOSED store to
// d_out (B,C,P). N=128 (full C), grid (1, M/128).
// =================================================================
__global__ __launch_bounds__(256, 2) void bgemm_fc2_tr_kernel(
    const __nv_bfloat16* __restrict__ A, const __nv_bfloat16* __restrict__ Bw,
    const float* __restrict__ bias, const float* __restrict__ ls,
    const float* __restrict__ resid, float* __restrict__ out)
{
    __shared__ __nv_bfloat16 As[128][LDS_S];
    __shared__ __nv_bfloat16 Bs[128][LDS_S];
    __shared__ float tsm[32][132];
    constexpr int K = 512;
    int tid = threadIdx.x, lane = tid & 31, w = tid >> 5;
    int wm = w & 1, wn = w >> 1;
    size_t rowBase = (size_t)blockIdx.y * 128;

    int ldRow = tid >> 1;
    int ldCol = (tid & 1) * 16;
    const __nv_bfloat16* Ap = A  + (rowBase + ldRow) * K + ldCol;
    const __nv_bfloat16* Bp = Bw + (size_t)ldRow * K + ldCol;

    float acc[4][4][4];
#pragma unroll
    for (int i = 0; i < 4; i++)
#pragma unroll
        for (int j = 0; j < 4; j++)
#pragma unroll
            for (int r = 0; r < 4; r++) acc[i][j][r] = 0.f;

    uint4 av0 = *(const uint4*)Ap, av1 = *(const uint4*)(Ap + 8);
    uint4 bv0 = *(const uint4*)Bp, bv1 = *(const uint4*)(Bp + 8);

    u32 sA = (u32)__cvta_generic_to_shared(&As[0][0]);
    u32 sB = (u32)__cvta_generic_to_shared(&Bs[0][0]);
    int arow = wm * 64 + (lane & 15);
    int brow = wn * 32 + (lane & 15);
    int csel = (lane >> 4) * 8;

    for (int kt = 0; kt < K; kt += 32) {
        __syncthreads();
        *(uint4*)&As[ldRow][ldCol]     = av0;
        *(uint4*)&As[ldRow][ldCol + 8] = av1;
        *(uint4*)&Bs[ldRow][ldCol]     = bv0;
        *(uint4*)&Bs[ldRow][ldCol + 8] = bv1;
        if (kt + 32 < K) {
            Ap += 32; Bp += 32;
            av0 = *(const uint4*)Ap; av1 = *(const uint4*)(Ap + 8);
            bv0 = *(const uint4*)Bp; bv1 = *(const uint4*)(Bp + 8);
        }
        __syncthreads();
#pragma unroll
        for (int kk = 0; kk < 32; kk += 16) {
            u32 af[4][4], bf[4][2];
            int acol = kk + csel;
#pragma unroll
            for (int mi = 0; mi < 4; mi++) {
                u32 addr = sA + (u32)(((arow + mi * 16) * LDS_S + acol) * 2);
                ldsm_x4(af[mi][0], af[mi][1], af[mi][2], af[mi][3], addr);
            }
#pragma unroll
            for (int np = 0; np < 2; np++) {
                u32 r0, r1, r2, r3;
                u32 addr = sB + (u32)(((brow + np * 16) * LDS_S + acol) * 2);
                ldsm_x4(r0, r1, r2, r3, addr);
                bf[np * 2][0]     = r0; bf[np * 2][1]     = r2;
                bf[np * 2 + 1][0] = r1; bf[np * 2 + 1][1] = r3;
            }
#pragma unroll
            for (int mi = 0; mi < 4; mi++)
#pragma unroll
                for (int nj = 0; nj < 4; nj++)
                    mma_bf16(acc[mi][nj], af[mi], bf[nj]);
        }
    }

    // epilogue: bias + ls + residual, then transposed write via smem
    int b  = (int)(rowBase / P);
    int p0 = (int)(rowBase % P);
#pragma unroll
    for (int cg = 0; cg < 4; cg++) {
        __syncthreads();
        if (wn == cg) {
#pragma unroll
            for (int mi = 0; mi < 4; mi++)
#pragma unroll
                for (int rp = 0; rp < 2; rp++) {
                    int pl = wm * 64 + mi * 16 + rp * 8 + (lane >> 2);
                    size_t grow = rowBase + pl;
#pragma unroll
                    for (int nj = 0; nj < 4; nj++) {
                        int cl = nj * 8 + (lane & 3) * 2;     // 0..31 in group
                        int cglob = cg * 32 + cl;
                        float2 bb = *(const float2*)(bias + cglob);
                        float2 ss = *(const float2*)(ls + cglob);
                        float2 rr = *(const float2*)(resid + grow * 128 + cglob);
                        tsm[cl][pl]     = rr.x + ss.x * (acc[mi][nj][rp*2]   + bb.x);
                        tsm[cl + 1][pl] = rr.y + ss.y * (acc[mi][nj][rp*2+1] + bb.y);
                    }
                }
        }
        __syncthreads();
        int c  = tid >> 3;
        int pj = (tid & 7) * 16;
        float* dst = out + (size_t)b * C * P + (size_t)(cg * 32 + c) * P + p0 + pj;
        const float* srcp = &tsm[c][pj];
#pragma unroll
        for (int j = 0; j < 4; j++)
            *(float4*)(dst + j * 4) = *(const float4*)(srcp + j * 4);
    }
}

// =================================================================
// Warp-level attention core (unchanged from R7)
// =================================================================
constexpr int AST = 24;

__device__ __forceinline__ void attn_warp(
    const __nv_bfloat16* Qs, const __nv_bfloat16* Ks, const __nv_bfloat16* Vs,
    int nchunks, int lane, float o[2][2][4], float rsum[2][2])
{
    const float scale = 0.25f;
    int g = lane >> 3, i = lane & 7;
    int r4 = lane >> 2, c4 = lane & 3;

    u32 aq[2][4];
#pragma unroll
    for (int mt = 0; mt < 2; mt++) {
        u32 addr = (u32)__cvta_generic_to_shared(
            Qs + (mt * 16 + (g & 1) * 8 + i) * AST + (g >> 1) * 8);
        ldsm_x4(aq[mt][0], aq[mt][1], aq[mt][2], aq[mt][3], addr);
    }

#pragma unroll
    for (int mt = 0; mt < 2; mt++)
#pragma unroll
        for (int nh = 0; nh < 2; nh++)
#pragma unroll
            for (int q = 0; q < 4; q++) o[mt][nh][q] = 0.f;
    rsum[0][0] = rsum[0][1] = rsum[1][0] = rsum[1][1] = 0.f;

    for (int ch = 0; ch < nchunks; ch++) {
        const __nv_bfloat16* Kc = Ks + ch * 64 * AST;
        const __nv_bfloat16* Vc = Vs + ch * 64 * AST;
        u32 pf[2][4][4];
#pragma unroll
        for (int nt = 0; nt < 8; nt++) {
            const __nv_bfloat16* kp = Kc + (nt * 8 + r4) * AST + c4 * 2;
            u32 bb[2];
            bb[0] = *(const u32*)kp;
            bb[1] = *(const u32*)(kp + 8);
            float s0[4] = {0.f, 0.f, 0.f, 0.f};
            float s1[4] = {0.f, 0.f, 0.f, 0.f};
            mma_bf16(s0, aq[0], bb);
            mma_bf16(s1, aq[1], bb);
            float e00 = __expf(s0[0] * scale), e01 = __expf(s0[1] * scale);
            float e02 = __expf(s0[2] * scale), e03 = __expf(s0[3] * scale);
            float e10 = __expf(s1[0] * scale), e11 = __expf(s1[1] * scale);
            float e12 = __expf(s1[2] * scale), e13 = __expf(s1[3] * scale);
            rsum[0][0] += e00 + e01;  rsum[0][1] += e02 + e03;
            rsum[1][0] += e10 + e11;  rsum[1][1] += e12 + e13;
            int kt = nt >> 1, lo = (nt & 1) * 2;
            pf[0][kt][lo + 0] = pack_bf16x2(e00, e01);
            pf[0][kt][lo + 1] = pack_bf16x2(e02, e03);
            pf[1][kt][lo + 0] = pack_bf16x2(e10, e11);
            pf[1][kt][lo + 1] = pack_bf16x2(e12, e13);
        }
#pragma unroll
        for (int kt = 0; kt < 4; kt++) {
            u32 v0, v1, v2, v3;
            u32 addr = (u32)__cvta_generic_to_shared(
                Vc + (kt * 16 + (g & 1) * 8 + i) * AST + (g >> 1) * 8);
            ldsm_x4_t(v0, v1, v2, v3, addr);
            u32 b0[2] = {v0, v1};
            u32 b1[2] = {v2, v3};
            mma_bf16(o[0][0], pf[0][kt], b0);
            mma_bf16(o[0][1], pf[0][kt], b1);
            mma_bf16(o[1][0], pf[1][kt], b0);
            mma_bf16(o[1][1], pf[1][kt], b1);
        }
    }

#pragma unroll
    for (int mt = 0; mt < 2; mt++)
#pragma unroll
        for (int hh = 0; hh < 2; hh++) {
            float v = rsum[mt][hh];
            v += __shfl_xor_sync(0xffffffffu, v, 1);
            v += __shfl_xor_sync(0xffffffffu, v, 2);
            rsum[mt][hh] = v;
        }
}

// =================================================================
// Window attention: CTA per (b, wy, wx); 4 heads x 2 warps.
// =================================================================
__global__ __launch_bounds__(256) void win_attn_kernel(
    const __nv_bfloat16* __restrict__ qkv, __nv_bfloat16* __restrict__ abuf)
{
    __shared__ __align__(16) __nv_bfloat16 Qs[4 * 64 * AST];
    __shared__ __align__(16) __nv_bfloat16 Ks[4 * 64 * AST];
    __shared__ __align__(16) __nv_bfloat16 Vs[4 * 64 * AST];

    int blk = blockIdx.x;
    int b  = blk >> 8;
    int wy = (blk >> 4) & 15;
    int wx = blk & 15;
    int tid = threadIdx.x;

    {
        int h = tid >> 6, t = tid & 63;
        int y = t >> 3, x = t & 7;
        size_t p = (size_t)(wy * 8 + y) * WW + wx * 8 + x;
        const __nv_bfloat16* base = qkv + ((size_t)b * P + p) * 384 + h * 16;
        int row = (h * 64 + t) * AST;
        const uint4* q4 = (const uint4*)base;
        const uint4* k4 = (const uint4*)(base + 128);
        const uint4* v4 = (const uint4*)(base + 256);
        *(uint4*)&Qs[row] = q4[0];  *(uint4*)&Qs[row + 8] = q4[1];
        *(uint4*)&Ks[row] = k4[0];  *(uint4*)&Ks[row + 8] = k4[1];
        *(uint4*)&Vs[row] = v4[0];  *(uint4*)&Vs[row + 8] = v4[1];
    }
    __syncthreads();

    int w = tid >> 5, lane = tid & 31;
    int h = w >> 1;
    int qb = (w & 1) * 32;

    float o[2][2][4], rsum[2][2];
    attn_warp(Qs + (h * 64 + qb) * AST, Ks + h * 64 * AST, Vs + h * 64 * AST,
              1, lane, o, rsum);

    int r4 = lane >> 2, c4 = lane & 3;
#pragma unroll
    for (int mt = 0; mt < 2; mt++) {
        float inv0 = 1.f / rsum[mt][0];
        float inv1 = 1.f / rsum[mt][1];
#pragma unroll
        for (int hh = 0; hh < 2; hh++) {
            int q = qb + mt * 16 + hh * 8 + r4;
            size_t p = (size_t)(wy * 8 + (q >> 3)) * WW + wx * 8 + (q & 7);
            float inv = hh ? inv1 : inv0;
            __nv_bfloat16* ob = abuf + ((size_t)b * P + p) * C + h * 16;
#pragma unroll
            for (int nh = 0; nh < 2; nh++) {
                float ox = o[mt][nh][hh * 2]     * inv;
                float oy = o[mt][nh][hh * 2 + 1] * inv;
                *(__nv_bfloat162*)(ob + nh * 8 + c4 * 2) = __floats2bfloat162_rn(ox, oy);
            }
        }
    }
}

// =================================================================
// Grid attention: CTA per (b, pos-in-window, head); 8 warps x 32 q.
// =================================================================
__global__ __launch_bounds__(256) void grid_attn_kernel(
    const __nv_bfloat16* __restrict__ qkv, __nv_bfloat16* __restrict__ abuf)
{
    __shared__ __align__(16) __nv_bfloat16 Qs[256 * AST];
    __shared__ __align__(16) __nv_bfloat16 Ks[256 * AST];
    __shared__ __align__(16) __nv_bfloat16 Vs[256 * AST];

    int blk = blockIdx.x;
    int b   = blk >> 8;
    int pos = (blk >> 2) & 63;
    int hg  = blk & 3;
    int y = pos >> 3, x = pos & 7;
    int tid = threadIdx.x;

    {
        int j = tid;
        int wy = j >> 4, wx = j & 15;
        size_t p = (size_t)(wy * 8 + y) * WW + wx * 8 + x;
        const __nv_bfloat16* base = qkv + ((size_t)b * P + p) * 384 + 64 + hg * 16;
        int row = j * AST;
        const uint4* q4 = (const uint4*)base;
        const uint4* k4 = (const uint4*)(base + 128);
        const uint4* v4 = (const uint4*)(base + 256);
        *(uint4*)&Qs[row] = q4[0];  *(uint4*)&Qs[row + 8] = q4[1];
        *(uint4*)&Ks[row] = k4[0];  *(uint4*)&Ks[row + 8] = k4[1];
        *(uint4*)&Vs[row] = v4[0];  *(uint4*)&Vs[row + 8] = v4[1];
    }
    __syncthreads();

    int w = tid >> 5, lane = tid & 31;
    int qb = w * 32;

    float o[2][2][4], rsum[2][2];
    attn_warp(Qs + qb * AST, Ks, Vs, 4, lane, o, rsum);

    int r4 = lane >> 2, c4 = lane & 3;
#pragma unroll
    for (int mt = 0; mt < 2; mt++) {
        float inv0 = 1.f / rsum[mt][0];
        float inv1 = 1.f / rsum[mt][1];
#pragma unroll
        for (int hh = 0; hh < 2; hh++) {
            int j = qb + mt * 16 + hh * 8 + r4;
            int wy = j >> 4, wx = j & 15;
            size_t p = (size_t)(wy * 8 + y) * WW + wx * 8 + x;
            float inv = hh ? inv1 : inv0;
            __nv_bfloat16* ob = abuf + ((size_t)b * P + p) * C + 64 + hg * 16;
#pragma unroll
            for (int nh = 0; nh < 2; nh++) {
                float ox = o[mt][nh][hh * 2]     * inv;
                float oy = o[mt][nh][hh * 2 + 1] * inv;
                *(__nv_bfloat162*)(ob + nh * 8 + c4 * 2) = __floats2bfloat162_rn(ox, oy);
            }
        }
    }
}

// =================================================================
// host launcher
// =================================================================
extern "C" void kernel_launch(void* const* d_in, const int* in_sizes, int n_in,
                              void* d_out, int out_size)
{
    const float* x       = (const float*)d_in[0];
    const float* conv_w  = (const float*)d_in[1];
    const float* conv_b  = (const float*)d_in[2];
    const float* norm1_w = (const float*)d_in[3];
    const float* norm1_b = (const float*)d_in[4];
    const float* wqkv    = (const float*)d_in[5];
    const float* proj_w  = (const float*)d_in[6];
    const float* proj_b  = (const float*)d_in[7];
    const float* norm2_w = (const float*)d_in[8];
    const float* norm2_b = (const float*)d_in[9];
    const float* fc1_w   = (const float*)d_in[10];
    const float* fc1_b   = (const float*)d_in[11];
    const float* fc2_w   = (const float*)d_in[12];
    const float* fc2_b   = (const float*)d_in[13];
    const float* ls1     = (const float*)d_in[14];
    const float* ls2     = (const float*)d_in[15];
    float* out = (float*)d_out;

    float *pxt, *pxt2;
    __nv_bfloat16 *pqkv, *pabuf, *ph, *pwq, *pwp, *pw1, *pw2;
    cudaGetSymbolAddress((void**)&pxt,   g_xt);
    cudaGetSymbolAddress((void**)&pqkv,  g_qkvb);
    cudaGetSymbolAddress((void**)&pabuf, g_abuf);
    cudaGetSymbolAddress((void**)&pxt2,  g_xt2);
    cudaGetSymbolAddress((void**)&ph,    g_h);
    cudaGetSymbolAddress((void**)&pwq,   g_wqkv_t);
    cudaGetSymbolAddress((void**)&pwp,   g_proj_t);
    cudaGetSymbolAddress((void**)&pw1,   g_fc1_t);
    cudaGetSymbolAddress((void**)&pw2,   g_fc2_t);

    // 0. all weight transposes in one launch
    wt_all_kernel<<<192, dim3(32, 8)>>>(wqkv, proj_w, fc1_w, fc2_w,
                                        pwq, pwp, pw1, pw2);

    // 1. conv + residual + transpose -> xt (fp32)
    conv_kernel<<<dim3(16, HH, BS), 256>>>(x, conv_w, conv_b, pxt);

    // 2. LN1 + QKV GEMM fused -> bf16 qkv
    {
        EpiQKVb e{pqkv};
        lngemm_kernel<EpiQKVb><<<dim3(3, (unsigned)(M / 128)), 256>>>(
            pxt, norm1_w, norm1_b, pwq, e);
    }

    // 3. attention (tensor-core) -> abuf (bf16)
    win_attn_kernel <<<BS * 256, 256>>>(pqkv, pabuf);
    grid_attn_kernel<<<BS * 256, 256>>>(pqkv, pabuf);

    // 4. proj GEMM + ls1 + residual -> xt2 (fp32)
    {
        EpiProj e{proj_b, ls1, pxt, pxt2};
        bgemm_kernel<EpiProj><<<dim3(1, (unsigned)(M / 128)), 256>>>(pabuf, pwp, 128, e);
    }

    // 5. LN2 + FC1 GEMM fused + bias + GELU -> h (bf16)
    {
        EpiGelu e{fc1_b, ph};
        lngemm_kernel<EpiGelu><<<dim3(4, (unsigned)(M / 128)), 256>>>(
            pxt2, norm2_w, norm2_b, pw1, e);
    }

    // 6. FC2 + bias + ls2 + residual + transposed store -> d_out
    bgemm_fc2_tr_kernel<<<dim3(1, (unsigned)(M / 128)), 256>>>(
        ph, pw2, fc2_b, ls2, pxt2, out);

    (void)in_sizes; (void)n_in; (void)out_size;
}

// round 10
// speedup vs baseline: 1.1346x; 1.1346x over previous
#include <cuda_runtime.h>
#include <cuda_bf16.h>
#include <math.h>
#include <stdint.h>
#include <string.h>

typedef unsigned int u32;

// ---------------- problem constants ----------------
constexpr int BS  = 8;
constexpr int C   = 128;
constexpr int HH  = 128;
constexpr int WW  = 128;
constexpr int P   = HH * WW;
constexpr long long M = (long long)BS * P;  // 131072 rows
constexpr int HID = 512;

// ---------------- device scratch ----------------
__device__ float          g_xt  [(size_t)M * C];       // residual stream (fp32)
__device__ __nv_bfloat16  g_qkvb[(size_t)M * 3 * C];   // qkv (bf16)
__device__ __nv_bfloat16  g_abuf[(size_t)M * C];       // attention out (bf16)
__device__ float          g_xt2 [(size_t)M * C];       // residual after attn (fp32)
__device__ __nv_bfloat16  g_h   [(size_t)M * HID];     // gelu(fc1) (bf16)

// transposed bf16 weights [N][K]
__device__ __nv_bfloat16  g_wqkv_t[384 * 128];
__device__ __nv_bfloat16  g_proj_t[128 * 128];
__device__ __nv_bfloat16  g_fc1_t [512 * 128];
__device__ __nv_bfloat16  g_fc2_t [128 * 512];

// =================================================================
// mma / ldmatrix primitives
// =================================================================
__device__ __forceinline__ void ldsm_x4(u32 &r0, u32 &r1, u32 &r2, u32 &r3, u32 addr)
{
    asm volatile("ldmatrix.sync.aligned.m8n8.x4.shared.b16 {%0,%1,%2,%3}, [%4];"
                 : "=r"(r0), "=r"(r1), "=r"(r2), "=r"(r3) : "r"(addr));
}
__device__ __forceinline__ void ldsm_x4_t(u32 &r0, u32 &r1, u32 &r2, u32 &r3, u32 addr)
{
    asm volatile("ldmatrix.sync.aligned.m8n8.x4.trans.shared.b16 {%0,%1,%2,%3}, [%4];"
                 : "=r"(r0), "=r"(r1), "=r"(r2), "=r"(r3) : "r"(addr));
}
__device__ __forceinline__ void mma_bf16(float* d, const u32* a, const u32* b)
{
    asm volatile("mma.sync.aligned.m16n8k16.row.col.f32.bf16.bf16.f32 "
                 "{%0,%1,%2,%3}, {%4,%5,%6,%7}, {%8,%9}, {%0,%1,%2,%3};"
                 : "+f"(d[0]), "+f"(d[1]), "+f"(d[2]), "+f"(d[3])
                 : "r"(a[0]), "r"(a[1]), "r"(a[2]), "r"(a[3]),
                   "r"(b[0]), "r"(b[1]));
}
__device__ __forceinline__ u32 pack_bf16x2(float a, float b)
{
    __nv_bfloat162 t = __floats2bfloat162_rn(a, b);
    u32 r;
    memcpy(&r, &t, 4);
    return r;
}

// =================================================================
// merged weight transpose + bf16 convert (all 4 weights, one launch)
// =================================================================
__global__ void wt_all_kernel(const float* __restrict__ wqkv, const float* __restrict__ projw,
                              const float* __restrict__ fc1w, const float* __restrict__ fc2w,
                              __nv_bfloat16* oq, __nv_bfloat16* op,
                              __nv_bfloat16* o1, __nv_bfloat16* o2)
{
    __shared__ float t[32][33];
    int id = blockIdx.x;
    const float* W; __nv_bfloat16* Wt; int K, N, local;
    if (id < 48)       { W = wqkv;  Wt = oq; K = 128; N = 384; local = id; }
    else if (id < 64)  { W = projw; Wt = op; K = 128; N = 128; local = id - 48; }
    else if (id < 128) { W = fc1w;  Wt = o1; K = 128; N = 512; local = id - 64; }
    else               { W = fc2w;  Wt = o2; K = 512; N = 128; local = id - 128; }
    int nTiles = N / 32;
    int n0 = (local % nTiles) * 32;
    int k0 = (local / nTiles) * 32;
    int tx = threadIdx.x, ty = threadIdx.y;
    for (int i = ty; i < 32; i += 8)
        t[i][tx] = W[(size_t)(k0 + i) * N + n0 + tx];
    __syncthreads();
    for (int i = ty; i < 32; i += 8)
        Wt[(size_t)(n0 + i) * K + k0 + tx] = __float2bfloat16(t[tx][i]);
}

// =================================================================
// Kernel 1: depthwise 3x3 conv + bias + residual -> xt (B,P,C) fp32
// =================================================================
__global__ __launch_bounds__(256) void conv_kernel(
    const float* __restrict__ x, const float* __restrict__ cw,
    const float* __restrict__ cb, float* __restrict__ xt)
{
    int b  = blockIdx.z;
    int h  = blockIdx.y;
    int c0 = (blockIdx.x >> 2) * 32;
    int w0 = (blockIdx.x & 3) * 32;
    __shared__ float sx[32][3][36];
    __shared__ float so[32][33];
    int tid = threadIdx.x;

    for (int i = tid; i < 32 * 3 * 34; i += 256) {
        int c  = i / (3 * 34);
        int r  = (i / 34) % 3;
        int wi = i % 34;
        int hh = h + r - 1;
        int wg = w0 + wi - 1;
        float v = 0.f;
        if (hh >= 0 && hh < HH && wg >= 0 && wg < WW)
            v = x[(((size_t)b * C + c0 + c) * HH + hh) * WW + wg];
        sx[c][r][wi] = v;
    }
    __syncthreads();

    int c     = tid >> 3;
    int wbase = (tid & 7) * 4;
    const float* wg9 = cw + (size_t)(c0 + c) * 9;
    float w00 = wg9[0], w01 = wg9[1], w02 = wg9[2];
    float w10 = wg9[3], w11 = wg9[4], w12 = wg9[5];
    float w20 = wg9[6], w21 = wg9[7], w22 = wg9[8];
    float bias = cb[c0 + c];
#pragma unroll
    for (int j = 0; j < 4; j++) {
        int wi = wbase + j;
        float acc = sx[c][0][wi] * w00 + sx[c][0][wi+1] * w01 + sx[c][0][wi+2] * w02
                  + sx[c][1][wi] * w10 + sx[c][1][wi+1] * w11 + sx[c][1][wi+2] * w12
                  + sx[c][2][wi] * w20 + sx[c][2][wi+1] * w21 + sx[c][2][wi+2] * w22;
        so[c][wi] = acc + bias + sx[c][1][wi+1];
    }
    __syncthreads();

    int cc = tid & 31;
    for (int wr = tid >> 5; wr < 32; wr += 8) {
        xt[((size_t)b * P + (size_t)h * WW + w0 + wr) * C + c0 + cc] = so[cc][wr];
    }
}

// =================================================================
// Epilogue functors
// =================================================================
struct EpiQKVb {   // qkv -> bf16
    __nv_bfloat16* out;
    __device__ __forceinline__ void store(size_t row, int col, float2 v) const {
        *(__nv_bfloat162*)(out + row * 384 + col) = __floats2bfloat162_rn(v.x, v.y);
    }
};
struct EpiProj {   // xt2 = xt + ls1 * (v + bias)   (fp32 out)
    const float* bias; const float* ls; const float* resid; float* out;
    __device__ __forceinline__ void store(size_t row, int col, float2 v) const {
        float2 bb = *(const float2*)(bias + col);
        float2 ss = *(const float2*)(ls + col);
        float2 rr = *(const float2*)(resid + row * 128 + col);
        float2 o;
        o.x = rr.x + ss.x * (v.x + bb.x);
        o.y = rr.y + ss.y * (v.y + bb.y);
        *(float2*)(out + row * 128 + col) = o;
    }
};
struct EpiGelu {   // h = gelu(v + bias)  -> bf16, N=512
    const float* bias; __nv_bfloat16* out;
    __device__ __forceinline__ float gelu(float g) const {
        return 0.5f * g * (1.f + erff(g * 0.70710678118654752f));
    }
    __device__ __forceinline__ void store(size_t row, int col, float2 v) const {
        float2 bb = *(const float2*)(bias + col);
        *(__nv_bfloat162*)(out + row * 512 + col) =
            __floats2bfloat162_rn(gelu(v.x + bb.x), gelu(v.y + bb.y));
    }
};

// =================================================================
// Fused LayerNorm + bf16 GEMM, K=128: LN computed ONCE, A-tile
// resident in smem; CTA loops over NCB column blocks of 128.
// grid = (M/128), 256 threads.
// =================================================================
constexpr int ASTR = 136;   // resident A row stride (17*16B -> ldsm conflict-free)
constexpr int LDS_S = 40;   // streamed tile row stride (5*16B)

template <int NCB, class Epi>
__global__ __launch_bounds__(256, 2) void lngemm_kernel(
    const float* __restrict__ A, const float* __restrict__ lnw,
    const float* __restrict__ lnb, const __nv_bfloat16* __restrict__ Bw,
    Epi epi)
{
    __shared__ __nv_bfloat16 As[128][ASTR];
    __shared__ __nv_bfloat16 Bs[128][LDS_S];
    int tid = threadIdx.x, lane = tid & 31, w = tid >> 5;
    int wm = w & 1, wn = w >> 1;
    size_t rowBase = (size_t)blockIdx.x * 128;

    // ---- LN stage: 2 threads per row, computed ONCE ----
    {
        int row = tid >> 1, half = tid & 1;
        const float4* src = (const float4*)(A + (rowBase + row) * 128 + half * 64);
        float s = 0.f, q = 0.f;
#pragma unroll
        for (int i = 0; i < 16; i++) {
            float4 v = src[i];
            s += v.x + v.y + v.z + v.w;
            q += v.x*v.x + v.y*v.y + v.z*v.z + v.w*v.w;
        }
        s += __shfl_xor_sync(0xffffffffu, s, 1);
        q += __shfl_xor_sync(0xffffffffu, q, 1);
        float mean = s * (1.f / 128.f);
        float var  = q * (1.f / 128.f) - mean * mean;
        float rstd = rsqrtf(var + 1e-5f);
        const float4* wp = (const float4*)(lnw + half * 64);
        const float4* bp = (const float4*)(lnb + half * 64);
#pragma unroll
        for (int j = 0; j < 8; j++) {
            float4 a  = src[2*j],  b2  = src[2*j+1];
            float4 w4 = wp[2*j],   w42 = wp[2*j+1];
            float4 b4 = bp[2*j],   b42 = bp[2*j+1];
            u32 o[4];
            o[0] = pack_bf16x2((a.x-mean)*rstd*w4.x + b4.x,  (a.y-mean)*rstd*w4.y + b4.y);
            o[1] = pack_bf16x2((a.z-mean)*rstd*w4.z + b4.z,  (a.w-mean)*rstd*w4.w + b4.w);
            o[2] = pack_bf16x2((b2.x-mean)*rstd*w42.x + b42.x,(b2.y-mean)*rstd*w42.y + b42.y);
            o[3] = pack_bf16x2((b2.z-mean)*rstd*w42.z + b42.z,(b2.w-mean)*rstd*w42.w + b42.w);
            *(uint4*)&As[row][half * 64 + j * 8] = *(uint4*)o;
        }
    }

    int ldRow = tid >> 1, ldCol = (tid & 1) * 16;
    u32 sA = (u32)__cvta_generic_to_shared(&As[0][0]);
    u32 sB = (u32)__cvta_generic_to_shared(&Bs[0][0]);
    int arow = wm * 64 + (lane & 15);
    int brow = wn * 32 + (lane & 15);
    int csel = (lane >> 4) * 8;

    uint4 bv0, bv1;
    {   // first tile prefetch (cb=0, s=0)
        const __nv_bfloat16* p = Bw + (size_t)ldRow * 128 + ldCol;
        bv0 = *(const uint4*)p; bv1 = *(const uint4*)(p + 8);
    }

#pragma unroll
    for (int cb = 0; cb < NCB; cb++) {
        int colBase = cb * 128;
        float acc[4][4][4];
#pragma unroll
        for (int i = 0; i < 4; i++)
#pragma unroll
            for (int j = 0; j < 4; j++)
#pragma unroll
                for (int r = 0; r < 4; r++) acc[i][j][r] = 0.f;

#pragma unroll
        for (int s = 0; s < 4; s++) {
            __syncthreads();
            *(uint4*)&Bs[ldRow][ldCol]     = bv0;
            *(uint4*)&Bs[ldRow][ldCol + 8] = bv1;
            // prefetch next tile (next stage or next column block)
            int ns = s + 1, ncb = cb;
            if (ns == 4) { ns = 0; ncb++; }
            if (ncb < NCB) {
                const __nv_bfloat16* p =
                    Bw + (size_t)(ncb * 128 + ldRow) * 128 + ns * 32 + ldCol;
                bv0 = *(const uint4*)p; bv1 = *(const uint4*)(p + 8);
            }
            __syncthreads();
#pragma unroll
            for (int kk2 = 0; kk2 < 2; kk2++) {
                int acol = s * 32 + kk2 * 16 + csel;
                int bcol = kk2 * 16 + csel;
                u32 af[4][4], bf[4][2];
#pragma unroll
                for (int mi = 0; mi < 4; mi++) {
                    u32 addr = sA + (u32)(((arow + mi * 16) * ASTR + acol) * 2);
                    ldsm_x4(af[mi][0], af[mi][1], af[mi][2], af[mi][3], addr);
                }
#pragma unroll
                for (int np = 0; np < 2; np++) {
                    u32 r0, r1, r2, r3;
                    u32 addr = sB + (u32)(((brow + np * 16) * LDS_S + bcol) * 2);
                    ldsm_x4(r0, r1, r2, r3, addr);
                    bf[np * 2][0]     = r0; bf[np * 2][1]     = r2;
                    bf[np * 2 + 1][0] = r1; bf[np * 2 + 1][1] = r3;
                }
#pragma unroll
                for (int mi = 0; mi < 4; mi++)
#pragma unroll
                    for (int nj = 0; nj < 4; nj++)
                        mma_bf16(acc[mi][nj], af[mi], bf[nj]);
            }
        }

#pragma unroll
        for (int mi = 0; mi < 4; mi++)
#pragma unroll
            for (int rp = 0; rp < 2; rp++) {
                size_t r = rowBase + wm * 64 + mi * 16 + rp * 8 + (lane >> 2);
#pragma unroll
                for (int nj = 0; nj < 4; nj++) {
                    int cgl = colBase + wn * 32 + nj * 8 + (lane & 3) * 2;
                    epi.store(r, cgl, make_float2(acc[mi][nj][rp * 2],
                                                  acc[mi][nj][rp * 2 + 1]));
                }
            }
    }
}

// =================================================================
// bf16 GEMM (A,B streamed) with functor epilogue — used for proj
// =================================================================
template <class Epi>
__global__ __launch_bounds__(256, 2) void bgemm_kernel(
    const __nv_bfloat16* __restrict__ A, const __nv_bfloat16* __restrict__ Bw,
    int K, Epi epi)
{
    __shared__ __nv_bfloat16 As[128][LDS_S];
    __shared__ __nv_bfloat16 Bs[128][LDS_S];
    int tid = threadIdx.x, lane = tid & 31, w = tid >> 5;
    int wm = w & 1, wn = w >> 1;
    size_t rowBase = (size_t)blockIdx.y * 128;
    int    colBase = blockIdx.x * 128;

    int ldRow = tid >> 1;
    int ldCol = (tid & 1) * 16;
    const __nv_bfloat16* Ap = A  + (rowBase + ldRow) * K + ldCol;
    const __nv_bfloat16* Bp = Bw + (size_t)(colBase + ldRow) * K + ldCol;

    float acc[4][4][4];
#pragma unroll
    for (int i = 0; i < 4; i++)
#pragma unroll
        for (int j = 0; j < 4; j++)
#pragma unroll
            for (int r = 0; r < 4; r++) acc[i][j][r] = 0.f;

    uint4 av0 = *(const uint4*)Ap, av1 = *(const uint4*)(Ap + 8);
    uint4 bv0 = *(const uint4*)Bp, bv1 = *(const uint4*)(Bp + 8);

    u32 sA = (u32)__cvta_generic_to_shared(&As[0][0]);
    u32 sB = (u32)__cvta_generic_to_shared(&Bs[0][0]);
    int arow = wm * 64 + (lane & 15);
    int brow = wn * 32 + (lane & 15);
    int csel = (lane >> 4) * 8;

    for (int kt = 0; kt < K; kt += 32) {
        __syncthreads();
        *(uint4*)&As[ldRow][ldCol]     = av0;
        *(uint4*)&As[ldRow][ldCol + 8] = av1;
        *(uint4*)&Bs[ldRow][ldCol]     = bv0;
        *(uint4*)&Bs[ldRow][ldCol + 8] = bv1;
        if (kt + 32 < K) {
            Ap += 32; Bp += 32;
            av0 = *(const uint4*)Ap; av1 = *(const uint4*)(Ap + 8);
            bv0 = *(const uint4*)Bp; bv1 = *(const uint4*)(Bp + 8);
        }
        __syncthreads();
#pragma unroll
        for (int kk = 0; kk < 32; kk += 16) {
            u32 af[4][4], bf[4][2];
            int acol = kk + csel;
#pragma unroll
            for (int mi = 0; mi < 4; mi++) {
                u32 addr = sA + (u32)(((arow + mi * 16) * LDS_S + acol) * 2);
                ldsm_x4(af[mi][0], af[mi][1], af[mi][2], af[mi][3], addr);
            }
#pragma unroll
            for (int np = 0; np < 2; np++) {
                u32 r0, r1, r2, r3;
                u32 addr = sB + (u32)(((brow + np * 16) * LDS_S + acol) * 2);
                ldsm_x4(r0, r1, r2, r3, addr);
                bf[np * 2][0]     = r0; bf[np * 2][1]     = r2;
                bf[np * 2 + 1][0] = r1; bf[np * 2 + 1][1] = r3;
            }
#pragma unroll
            for (int mi = 0; mi < 4; mi++)
#pragma unroll
                for (int nj = 0; nj < 4; nj++)
                    mma_bf16(acc[mi][nj], af[mi], bf[nj]);
        }
    }

#pragma unroll
    for (int mi = 0; mi < 4; mi++)
#pragma unroll
        for (int rp = 0; rp < 2; rp++) {
            size_t r = rowBase + wm * 64 + mi * 16 + rp * 8 + (lane >> 2);
#pragma unroll
            for (int nj = 0; nj < 4; nj++) {
                int cgl = colBase + wn * 32 + nj * 8 + (lane & 3) * 2;
                epi.store(r, cgl, make_float2(acc[mi][nj][rp * 2],
                                              acc[mi][nj][rp * 2 + 1]));
            }
        }
}

// =================================================================
// FC2 GEMM (K=512) + bias + ls2 + residual + TRANSPOSED store to
// d_out (B,C,P). N=128 (full C), grid (1, M/128).
// =================================================================
__global__ __launch_bounds__(256, 2) void bgemm_fc2_tr_kernel(
    const __nv_bfloat16* __restrict__ A, const __nv_bfloat16* __restrict__ Bw,
    const float* __restrict__ bias, const float* __restrict__ ls,
    const float* __restrict__ resid, float* __restrict__ out)
{
    __shared__ __nv_bfloat16 As[128][LDS_S];
    __shared__ __nv_bfloat16 Bs[128][LDS_S];
    __shared__ float tsm[32][132];
    constexpr int K = 512;
    int tid = threadIdx.x, lane = tid & 31, w = tid >> 5;
    int wm = w & 1, wn = w >> 1;
    size_t rowBase = (size_t)blockIdx.y * 128;

    int ldRow = tid >> 1;
    int ldCol = (tid & 1) * 16;
    const __nv_bfloat16* Ap = A  + (rowBase + ldRow) * K + ldCol;
    const __nv_bfloat16* Bp = Bw + (size_t)ldRow * K + ldCol;

    float acc[4][4][4];
#pragma unroll
    for (int i = 0; i < 4; i++)
#pragma unroll
        for (int j = 0; j < 4; j++)
#pragma unroll
            for (int r = 0; r < 4; r++) acc[i][j][r] = 0.f;

    uint4 av0 = *(const uint4*)Ap, av1 = *(const uint4*)(Ap + 8);
    uint4 bv0 = *(const uint4*)Bp, bv1 = *(const uint4*)(Bp + 8);

    u32 sA = (u32)__cvta_generic_to_shared(&As[0][0]);
    u32 sB = (u32)__cvta_generic_to_shared(&Bs[0][0]);
    int arow = wm * 64 + (lane & 15);
    int brow = wn * 32 + (lane & 15);
    int csel = (lane >> 4) * 8;

    for (int kt = 0; kt < K; kt += 32) {
        __syncthreads();
        *(uint4*)&As[ldRow][ldCol]     = av0;
        *(uint4*)&As[ldRow][ldCol + 8] = av1;
        *(uint4*)&Bs[ldRow][ldCol]     = bv0;
        *(uint4*)&Bs[ldRow][ldCol + 8] = bv1;
        if (kt + 32 < K) {
            Ap += 32; Bp += 32;
            av0 = *(const uint4*)Ap; av1 = *(const uint4*)(Ap + 8);
            bv0 = *(const uint4*)Bp; bv1 = *(const uint4*)(Bp + 8);
        }
        __syncthreads();
#pragma unroll
        for (int kk = 0; kk < 32; kk += 16) {
            u32 af[4][4], bf[4][2];
            int acol = kk + csel;
#pragma unroll
            for (int mi = 0; mi < 4; mi++) {
                u32 addr = sA + (u32)(((arow + mi * 16) * LDS_S + acol) * 2);
                ldsm_x4(af[mi][0], af[mi][1], af[mi][2], af[mi][3], addr);
            }
#pragma unroll
            for (int np = 0; np < 2; np++) {
                u32 r0, r1, r2, r3;
                u32 addr = sB + (u32)(((brow + np * 16) * LDS_S + acol) * 2);
                ldsm_x4(r0, r1, r2, r3, addr);
                bf[np * 2][0]     = r0; bf[np * 2][1]     = r2;
                bf[np * 2 + 1][0] = r1; bf[np * 2 + 1][1] = r3;
            }
#pragma unroll
            for (int mi = 0; mi < 4; mi++)
#pragma unroll
                for (int nj = 0; nj < 4; nj++)
                    mma_bf16(acc[mi][nj], af[mi], bf[nj]);
        }
    }

    // epilogue: bias + ls + residual, then transposed write via smem
    int b  = (int)(rowBase / P);
    int p0 = (int)(rowBase % P);
#pragma unroll
    for (int cg = 0; cg < 4; cg++) {
        __syncthreads();
        if (wn == cg) {
#pragma unroll
            for (int mi = 0; mi < 4; mi++)
#pragma unroll
                for (int rp = 0; rp < 2; rp++) {
                    int pl = wm * 64 + mi * 16 + rp * 8 + (lane >> 2);
                    size_t grow = rowBase + pl;
#pragma unroll
                    for (int nj = 0; nj < 4; nj++) {
                        int cl = nj * 8 + (lane & 3) * 2;     // 0..31 in group
                        int cglob = cg * 32 + cl;
                        float2 bb = *(const float2*)(bias + cglob);
                        float2 ss = *(const float2*)(ls + cglob);
                        float2 rr = *(const float2*)(resid + grow * 128 + cglob);
                        tsm[cl][pl]     = rr.x + ss.x * (acc[mi][nj][rp*2]   + bb.x);
                        tsm[cl + 1][pl] = rr.y + ss.y * (acc[mi][nj][rp*2+1] + bb.y);
                    }
                }
        }
        __syncthreads();
        int c  = tid >> 3;
        int pj = (tid & 7) * 16;
        float* dst = out + (size_t)b * C * P + (size_t)(cg * 32 + c) * P + p0 + pj;
        const float* srcp = &tsm[c][pj];
#pragma unroll
        for (int j = 0; j < 4; j++)
            *(float4*)(dst + j * 4) = *(const float4*)(srcp + j * 4);
    }
}

// =================================================================
// Warp-level attention core
// =================================================================
constexpr int AST = 24;

__device__ __forceinline__ void attn_warp(
    const __nv_bfloat16* Qs, const __nv_bfloat16* Ks, const __nv_bfloat16* Vs,
    int nchunks, int lane, float o[2][2][4], float rsum[2][2])
{
    const float scale = 0.25f;
    int g = lane >> 3, i = lane & 7;
    int r4 = lane >> 2, c4 = lane & 3;

    u32 aq[2][4];
#pragma unroll
    for (int mt = 0; mt < 2; mt++) {
        u32 addr = (u32)__cvta_generic_to_shared(
            Qs + (mt * 16 + (g & 1) * 8 + i) * AST + (g >> 1) * 8);
        ldsm_x4(aq[mt][0], aq[mt][1], aq[mt][2], aq[mt][3], addr);
    }

#pragma unroll
    for (int mt = 0; mt < 2; mt++)
#pragma unroll
        for (int nh = 0; nh < 2; nh++)
#pragma unroll
            for (int q = 0; q < 4; q++) o[mt][nh][q] = 0.f;
    rsum[0][0] = rsum[0][1] = rsum[1][0] = rsum[1][1] = 0.f;

    for (int ch = 0; ch < nchunks; ch++) {
        const __nv_bfloat16* Kc = Ks + ch * 64 * AST;
        const __nv_bfloat16* Vc = Vs + ch * 64 * AST;
        u32 pf[2][4][4];
#pragma unroll
        for (int nt = 0; nt < 8; nt++) {
            const __nv_bfloat16* kp = Kc + (nt * 8 + r4) * AST + c4 * 2;
            u32 bb[2];
            bb[0] = *(const u32*)kp;
            bb[1] = *(const u32*)(kp + 8);
            float s0[4] = {0.f, 0.f, 0.f, 0.f};
            float s1[4] = {0.f, 0.f, 0.f, 0.f};
            mma_bf16(s0, aq[0], bb);
            mma_bf16(s1, aq[1], bb);
            float e00 = __expf(s0[0] * scale), e01 = __expf(s0[1] * scale);
            float e02 = __expf(s0[2] * scale), e03 = __expf(s0[3] * scale);
            float e10 = __expf(s1[0] * scale), e11 = __expf(s1[1] * scale);
            float e12 = __expf(s1[2] * scale), e13 = __expf(s1[3] * scale);
            rsum[0][0] += e00 + e01;  rsum[0][1] += e02 + e03;
            rsum[1][0] += e10 + e11;  rsum[1][1] += e12 + e13;
            int kt = nt >> 1, lo = (nt & 1) * 2;
            pf[0][kt][lo + 0] = pack_bf16x2(e00, e01);
            pf[0][kt][lo + 1] = pack_bf16x2(e02, e03);
            pf[1][kt][lo + 0] = pack_bf16x2(e10, e11);
            pf[1][kt][lo + 1] = pack_bf16x2(e12, e13);
        }
#pragma unroll
        for (int kt = 0; kt < 4; kt++) {
            u32 v0, v1, v2, v3;
            u32 addr = (u32)__cvta_generic_to_shared(
                Vc + (kt * 16 + (g & 1) * 8 + i) * AST + (g >> 1) * 8);
            ldsm_x4_t(v0, v1, v2, v3, addr);
            u32 b0[2] = {v0, v1};
            u32 b1[2] = {v2, v3};
            mma_bf16(o[0][0], pf[0][kt], b0);
            mma_bf16(o[0][1], pf[0][kt], b1);
            mma_bf16(o[1][0], pf[1][kt], b0);
            mma_bf16(o[1][1], pf[1][kt], b1);
        }
    }

#pragma unroll
    for (int mt = 0; mt < 2; mt++)
#pragma unroll
        for (int hh = 0; hh < 2; hh++) {
            float v = rsum[mt][hh];
            v += __shfl_xor_sync(0xffffffffu, v, 1);
            v += __shfl_xor_sync(0xffffffffu, v, 2);
            rsum[mt][hh] = v;
        }
}

// =================================================================
// Window attention: CTA per (b, wy, wx); 4 heads x 2 warps.
// =================================================================
__global__ __launch_bounds__(256) void win_attn_kernel(
    const __nv_bfloat16* __restrict__ qkv, __nv_bfloat16* __restrict__ abuf)
{
    __shared__ __align__(16) __nv_bfloat16 Qs[4 * 64 * AST];
    __shared__ __align__(16) __nv_bfloat16 Ks[4 * 64 * AST];
    __shared__ __align__(16) __nv_bfloat16 Vs[4 * 64 * AST];

    int blk = blockIdx.x;
    int b  = blk >> 8;
    int wy = (blk >> 4) & 15;
    int wx = blk & 15;
    int tid = threadIdx.x;

    {
        int h = tid >> 6, t = tid & 63;
        int y = t >> 3, x = t & 7;
        size_t p = (size_t)(wy * 8 + y) * WW + wx * 8 + x;
        const __nv_bfloat16* base = qkv + ((size_t)b * P + p) * 384 + h * 16;
        int row = (h * 64 + t) * AST;
        const uint4* q4 = (const uint4*)base;
        const uint4* k4 = (const uint4*)(base + 128);
        const uint4* v4 = (const uint4*)(base + 256);
        *(uint4*)&Qs[row] = q4[0];  *(uint4*)&Qs[row + 8] = q4[1];
        *(uint4*)&Ks[row] = k4[0];  *(uint4*)&Ks[row + 8] = k4[1];
        *(uint4*)&Vs[row] = v4[0];  *(uint4*)&Vs[row + 8] = v4[1];
    }
    __syncthreads();

    int w = tid >> 5, lane = tid & 31;
    int h = w >> 1;
    int qb = (w & 1) * 32;

    float o[2][2][4], rsum[2][2];
    attn_warp(Qs + (h * 64 + qb) * AST, Ks + h * 64 * AST, Vs + h * 64 * AST,
              1, lane, o, rsum);

    int r4 = lane >> 2, c4 = lane & 3;
#pragma unroll
    for (int mt = 0; mt < 2; mt++) {
        float inv0 = 1.f / rsum[mt][0];
        float inv1 = 1.f / rsum[mt][1];
#pragma unroll
        for (int hh = 0; hh < 2; hh++) {
            int q = qb + mt * 16 + hh * 8 + r4;
            size_t p = (size_t)(wy * 8 + (q >> 3)) * WW + wx * 8 + (q & 7);
            float inv = hh ? inv1 : inv0;
            __nv_bfloat16* ob = abuf + ((size_t)b * P + p) * C + h * 16;
#pragma unroll
            for (int nh = 0; nh < 2; nh++) {
                float ox = o[mt][nh][hh * 2]     * inv;
                float oy = o[mt][nh][hh * 2 + 1] * inv;
                *(__nv_bfloat162*)(ob + nh * 8 + c4 * 2) = __floats2bfloat162_rn(ox, oy);
            }
        }
    }
}

// =================================================================
// Grid attention: CTA per (b, pos-in-window, head); 8 warps x 32 q.
// =================================================================
__global__ __launch_bounds__(256) void grid_attn_kernel(
    const __nv_bfloat16* __restrict__ qkv, __nv_bfloat16* __restrict__ abuf)
{
    __shared__ __align__(16) __nv_bfloat16 Qs[256 * AST];
    __shared__ __align__(16) __nv_bfloat16 Ks[256 * AST];
    __shared__ __align__(16) __nv_bfloat16 Vs[256 * AST];

    int blk = blockIdx.x;
    int b   = blk >> 8;
    int pos = (blk >> 2) & 63;
    int hg  = blk & 3;
    int y = pos >> 3, x = pos & 7;
    int tid = threadIdx.x;

    {
        int j = tid;
        int wy = j >> 4, wx = j & 15;
        size_t p = (size_t)(wy * 8 + y) * WW + wx * 8 + x;
        const __nv_bfloat16* base = qkv + ((size_t)b * P + p) * 384 + 64 + hg * 16;
        int row = j * AST;
        const uint4* q4 = (const uint4*)base;
        const uint4* k4 = (const uint4*)(base + 128);
        const uint4* v4 = (const uint4*)(base + 256);
        *(uint4*)&Qs[row] = q4[0];  *(uint4*)&Qs[row + 8] = q4[1];
        *(uint4*)&Ks[row] = k4[0];  *(uint4*)&Ks[row + 8] = k4[1];
        *(uint4*)&Vs[row] = v4[0];  *(uint4*)&Vs[row + 8] = v4[1];
    }
    __syncthreads();

    int w = tid >> 5, lane = tid & 31;
    int qb = w * 32;

    float o[2][2][4], rsum[2][2];
    attn_warp(Qs + qb * AST, Ks, Vs, 4, lane, o, rsum);

    int r4 = lane >> 2, c4 = lane & 3;
#pragma unroll
    for (int mt = 0; mt < 2; mt++) {
        float inv0 = 1.f / rsum[mt][0];
        float inv1 = 1.f / rsum[mt][1];
#pragma unroll
        for (int hh = 0; hh < 2; hh++) {
            int j = qb + mt * 16 + hh * 8 + r4;
            int wy = j >> 4, wx = j & 15;
            size_t p = (size_t)(wy * 8 + y) * WW + wx * 8 + x;
            float inv = hh ? inv1 : inv0;
            __nv_bfloat16* ob = abuf + ((size_t)b * P + p) * C + 64 + hg * 16;
#pragma unroll
            for (int nh = 0; nh < 2; nh++) {
                float ox = o[mt][nh][hh * 2]     * inv;
                float oy = o[mt][nh][hh * 2 + 1] * inv;
                *(__nv_bfloat162*)(ob + nh * 8 + c4 * 2) = __floats2bfloat162_rn(ox, oy);
            }
        }
    }
}

// =================================================================
// host launcher
// =================================================================
extern "C" void kernel_launch(void* const* d_in, const int* in_sizes, int n_in,
                              void* d_out, int out_size)
{
    const float* x       = (const float*)d_in[0];
    const float* conv_w  = (const float*)d_in[1];
    const float* conv_b  = (const float*)d_in[2];
    const float* norm1_w = (const float*)d_in[3];
    const float* norm1_b = (const float*)d_in[4];
    const float* wqkv    = (const float*)d_in[5];
    const float* proj_w  = (const float*)d_in[6];
    const float* proj_b  = (const float*)d_in[7];
    const float* norm2_w = (const float*)d_in[8];
    const float* norm2_b = (const float*)d_in[9];
    const float* fc1_w   = (const float*)d_in[10];
    const float* fc1_b   = (const float*)d_in[11];
    const float* fc2_w   = (const float*)d_in[12];
    const float* fc2_b   = (const float*)d_in[13];
    const float* ls1     = (const float*)d_in[14];
    const float* ls2     = (const float*)d_in[15];
    float* out = (float*)d_out;

    float *pxt, *pxt2;
    __nv_bfloat16 *pqkv, *pabuf, *ph, *pwq, *pwp, *pw1, *pw2;
    cudaGetSymbolAddress((void**)&pxt,   g_xt);
    cudaGetSymbolAddress((void**)&pqkv,  g_qkvb);
    cudaGetSymbolAddress((void**)&pabuf, g_abuf);
    cudaGetSymbolAddress((void**)&pxt2,  g_xt2);
    cudaGetSymbolAddress((void**)&ph,    g_h);
    cudaGetSymbolAddress((void**)&pwq,   g_wqkv_t);
    cudaGetSymbolAddress((void**)&pwp,   g_proj_t);
    cudaGetSymbolAddress((void**)&pw1,   g_fc1_t);
    cudaGetSymbolAddress((void**)&pw2,   g_fc2_t);

    // 0. all weight transposes in one launch
    wt_all_kernel<<<192, dim3(32, 8)>>>(wqkv, proj_w, fc1_w, fc2_w,
                                        pwq, pwp, pw1, pw2);

    // 1. conv + residual + transpose -> xt (fp32)
    conv_kernel<<<dim3(16, HH, BS), 256>>>(x, conv_w, conv_b, pxt);

    // 2. LN1 + QKV GEMM fused (LN once, 3 column blocks in-kernel)
    {
        EpiQKVb e{pqkv};
        lngemm_kernel<3, EpiQKVb><<<(unsigned)(M / 128), 256>>>(
            pxt, norm1_w, norm1_b, pwq, e);
    }

    // 3. attention (tensor-core) -> abuf (bf16)
    win_attn_kernel <<<BS * 256, 256>>>(pqkv, pabuf);
    grid_attn_kernel<<<BS * 256, 256>>>(pqkv, pabuf);

    // 4. proj GEMM + ls1 + residual -> xt2 (fp32)
    {
        EpiProj e{proj_b, ls1, pxt, pxt2};
        bgemm_kernel<EpiProj><<<dim3(1, (unsigned)(M / 128)), 256>>>(pabuf, pwp, 128, e);
    }

    // 5. LN2 + FC1 GEMM fused (LN once, 4 column blocks in-kernel)
    {
        EpiGelu e{fc1_b, ph};
        lngemm_kernel<4, EpiGelu><<<(unsigned)(M / 128), 256>>>(
            pxt2, norm2_w, norm2_b, pw1, e);
    }

    // 6. FC2 + bias + ls2 + residual + transposed store -> d_out
    bgemm_fc2_tr_kernel<<<dim3(1, (unsigned)(M / 128)), 256>>>(
        ph, pw2, fc2_b, ls2, pxt2, out);

    (void)in_sizes; (void)n_in; (void)out_size;
}

// round 11
// speedup vs baseline: 1.1974x; 1.0554x over previous
#include <cuda_runtime.h>
#include <cuda_bf16.h>
#include <math.h>
#include <stdint.h>
#include <string.h>

typedef unsigned int u32;

// ---------------- problem constants ----------------
constexpr int BS  = 8;
constexpr int C   = 128;
constexpr int HH  = 128;
constexpr int WW  = 128;
constexpr int P   = HH * WW;
constexpr long long M = (long long)BS * P;  // 131072 rows
constexpr int HID = 512;

// ---------------- device scratch ----------------
__device__ float          g_xt  [(size_t)M * C];       // residual stream (fp32)
__device__ __nv_bfloat16  g_qkvb[(size_t)M * 3 * C];   // qkv (bf16)
__device__ __nv_bfloat16  g_abuf[(size_t)M * C];       // attention out (bf16)
__device__ float          g_xt2 [(size_t)M * C];       // residual after attn (fp32)
__device__ __nv_bfloat16  g_h   [(size_t)M * HID];     // gelu(fc1) (bf16)

// transposed bf16 weights [N][K]
__device__ __nv_bfloat16  g_wqkv_t[384 * 128];
__device__ __nv_bfloat16  g_proj_t[128 * 128];
__device__ __nv_bfloat16  g_fc1_t [512 * 128];
__device__ __nv_bfloat16  g_fc2_t [128 * 512];

// =================================================================
// mma / ldmatrix primitives
// =================================================================
__device__ __forceinline__ void ldsm_x4(u32 &r0, u32 &r1, u32 &r2, u32 &r3, u32 addr)
{
    asm volatile("ldmatrix.sync.aligned.m8n8.x4.shared.b16 {%0,%1,%2,%3}, [%4];"
                 : "=r"(r0), "=r"(r1), "=r"(r2), "=r"(r3) : "r"(addr));
}
__device__ __forceinline__ void ldsm_x4_t(u32 &r0, u32 &r1, u32 &r2, u32 &r3, u32 addr)
{
    asm volatile("ldmatrix.sync.aligned.m8n8.x4.trans.shared.b16 {%0,%1,%2,%3}, [%4];"
                 : "=r"(r0), "=r"(r1), "=r"(r2), "=r"(r3) : "r"(addr));
}
__device__ __forceinline__ void mma_bf16(float* d, const u32* a, const u32* b)
{
    asm volatile("mma.sync.aligned.m16n8k16.row.col.f32.bf16.bf16.f32 "
                 "{%0,%1,%2,%3}, {%4,%5,%6,%7}, {%8,%9}, {%0,%1,%2,%3};"
                 : "+f"(d[0]), "+f"(d[1]), "+f"(d[2]), "+f"(d[3])
                 : "r"(a[0]), "r"(a[1]), "r"(a[2]), "r"(a[3]),
                   "r"(b[0]), "r"(b[1]));
}
__device__ __forceinline__ u32 pack_bf16x2(float a, float b)
{
    __nv_bfloat162 t = __floats2bfloat162_rn(a, b);
    u32 r;
    memcpy(&r, &t, 4);
    return r;
}

// =================================================================
// merged weight transpose + bf16 convert (all 4 weights, one launch)
// =================================================================
__global__ void wt_all_kernel(const float* __restrict__ wqkv, const float* __restrict__ projw,
                              const float* __restrict__ fc1w, const float* __restrict__ fc2w,
                              __nv_bfloat16* oq, __nv_bfloat16* op,
                              __nv_bfloat16* o1, __nv_bfloat16* o2)
{
    __shared__ float t[32][33];
    int id = blockIdx.x;
    const float* W; __nv_bfloat16* Wt; int K, N, local;
    if (id < 48)       { W = wqkv;  Wt = oq; K = 128; N = 384; local = id; }
    else if (id < 64)  { W = projw; Wt = op; K = 128; N = 128; local = id - 48; }
    else if (id < 128) { W = fc1w;  Wt = o1; K = 128; N = 512; local = id - 64; }
    else               { W = fc2w;  Wt = o2; K = 512; N = 128; local = id - 128; }
    int nTiles = N / 32;
    int n0 = (local % nTiles) * 32;
    int k0 = (local / nTiles) * 32;
    int tx = threadIdx.x, ty = threadIdx.y;
    for (int i = ty; i < 32; i += 8)
        t[i][tx] = W[(size_t)(k0 + i) * N + n0 + tx];
    __syncthreads();
    for (int i = ty; i < 32; i += 8)
        Wt[(size_t)(n0 + i) * K + k0 + tx] = __float2bfloat16(t[tx][i]);
}

// =================================================================
// Kernel 1: depthwise 3x3 conv + bias + residual -> xt (B,P,C) fp32
// =================================================================
__global__ __launch_bounds__(256) void conv_kernel(
    const float* __restrict__ x, const float* __restrict__ cw,
    const float* __restrict__ cb, float* __restrict__ xt)
{
    int b  = blockIdx.z;
    int h  = blockIdx.y;
    int c0 = (blockIdx.x >> 2) * 32;
    int w0 = (blockIdx.x & 3) * 32;
    __shared__ float sx[32][3][36];
    __shared__ float so[32][33];
    int tid = threadIdx.x;

    for (int i = tid; i < 32 * 3 * 34; i += 256) {
        int c  = i / (3 * 34);
        int r  = (i / 34) % 3;
        int wi = i % 34;
        int hh = h + r - 1;
        int wg = w0 + wi - 1;
        float v = 0.f;
        if (hh >= 0 && hh < HH && wg >= 0 && wg < WW)
            v = x[(((size_t)b * C + c0 + c) * HH + hh) * WW + wg];
        sx[c][r][wi] = v;
    }
    __syncthreads();

    int c     = tid >> 3;
    int wbase = (tid & 7) * 4;
    const float* wg9 = cw + (size_t)(c0 + c) * 9;
    float w00 = wg9[0], w01 = wg9[1], w02 = wg9[2];
    float w10 = wg9[3], w11 = wg9[4], w12 = wg9[5];
    float w20 = wg9[6], w21 = wg9[7], w22 = wg9[8];
    float bias = cb[c0 + c];
#pragma unroll
    for (int j = 0; j < 4; j++) {
        int wi = wbase + j;
        float acc = sx[c][0][wi] * w00 + sx[c][0][wi+1] * w01 + sx[c][0][wi+2] * w02
                  + sx[c][1][wi] * w10 + sx[c][1][wi+1] * w11 + sx[c][1][wi+2] * w12
                  + sx[c][2][wi] * w20 + sx[c][2][wi+1] * w21 + sx[c][2][wi+2] * w22;
        so[c][wi] = acc + bias + sx[c][1][wi+1];
    }
    __syncthreads();

    int cc = tid & 31;
    for (int wr = tid >> 5; wr < 32; wr += 8) {
        xt[((size_t)b * P + (size_t)h * WW + w0 + wr) * C + c0 + cc] = so[cc][wr];
    }
}

// =================================================================
// Epilogue functors
// =================================================================
struct EpiQKVb {   // qkv -> bf16
    __nv_bfloat16* out;
    __device__ __forceinline__ void store(size_t row, int col, float2 v) const {
        *(__nv_bfloat162*)(out + row * 384 + col) = __floats2bfloat162_rn(v.x, v.y);
    }
};
struct EpiProj {   // xt2 = xt + ls1 * (v + bias)   (fp32 out)
    const float* bias; const float* ls; const float* resid; float* out;
    __device__ __forceinline__ void store(size_t row, int col, float2 v) const {
        float2 bb = *(const float2*)(bias + col);
        float2 ss = *(const float2*)(ls + col);
        float2 rr = *(const float2*)(resid + row * 128 + col);
        float2 o;
        o.x = rr.x + ss.x * (v.x + bb.x);
        o.y = rr.y + ss.y * (v.y + bb.y);
        *(float2*)(out + row * 128 + col) = o;
    }
};
struct EpiGelu {   // h = gelu(v + bias)  -> bf16, N=512
    const float* bias; __nv_bfloat16* out;
    __device__ __forceinline__ float gelu(float g) const {
        return 0.5f * g * (1.f + erff(g * 0.70710678118654752f));
    }
    __device__ __forceinline__ void store(size_t row, int col, float2 v) const {
        float2 bb = *(const float2*)(bias + col);
        *(__nv_bfloat162*)(out + row * 512 + col) =
            __floats2bfloat162_rn(gelu(v.x + bb.x), gelu(v.y + bb.y));
    }
};

// =================================================================
// Fused LayerNorm + bf16 GEMM, K=128: LN once, A resident in smem,
// B double-buffered (ONE barrier per k-stage).
// grid = (M/128), 256 threads.
// =================================================================
constexpr int ASTR = 136;   // resident A row stride
constexpr int LDS_S = 40;   // streamed tile row stride

template <int NCB, class Epi>
__global__ __launch_bounds__(256, 2) void lngemm_kernel(
    const float* __restrict__ A, const float* __restrict__ lnw,
    const float* __restrict__ lnb, const __nv_bfloat16* __restrict__ Bw,
    Epi epi)
{
    __shared__ __nv_bfloat16 As[128][ASTR];
    __shared__ __nv_bfloat16 Bs[2][128][LDS_S];
    int tid = threadIdx.x, lane = tid & 31, w = tid >> 5;
    int wm = w & 1, wn = w >> 1;
    size_t rowBase = (size_t)blockIdx.x * 128;

    // ---- LN stage: 2 threads per row, computed ONCE ----
    {
        int row = tid >> 1, half = tid & 1;
        const float4* src = (const float4*)(A + (rowBase + row) * 128 + half * 64);
        float s = 0.f, q = 0.f;
#pragma unroll
        for (int i = 0; i < 16; i++) {
            float4 v = src[i];
            s += v.x + v.y + v.z + v.w;
            q += v.x*v.x + v.y*v.y + v.z*v.z + v.w*v.w;
        }
        s += __shfl_xor_sync(0xffffffffu, s, 1);
        q += __shfl_xor_sync(0xffffffffu, q, 1);
        float mean = s * (1.f / 128.f);
        float var  = q * (1.f / 128.f) - mean * mean;
        float rstd = rsqrtf(var + 1e-5f);
        const float4* wp = (const float4*)(lnw + half * 64);
        const float4* bp = (const float4*)(lnb + half * 64);
#pragma unroll
        for (int j = 0; j < 8; j++) {
            float4 a  = src[2*j],  b2  = src[2*j+1];
            float4 w4 = wp[2*j],   w42 = wp[2*j+1];
            float4 b4 = bp[2*j],   b42 = bp[2*j+1];
            u32 o[4];
            o[0] = pack_bf16x2((a.x-mean)*rstd*w4.x + b4.x,  (a.y-mean)*rstd*w4.y + b4.y);
            o[1] = pack_bf16x2((a.z-mean)*rstd*w4.z + b4.z,  (a.w-mean)*rstd*w4.w + b4.w);
            o[2] = pack_bf16x2((b2.x-mean)*rstd*w42.x + b42.x,(b2.y-mean)*rstd*w42.y + b42.y);
            o[3] = pack_bf16x2((b2.z-mean)*rstd*w42.z + b42.z,(b2.w-mean)*rstd*w42.w + b42.w);
            *(uint4*)&As[row][half * 64 + j * 8] = *(uint4*)o;
        }
    }

    int ldRow = tid >> 1, ldCol = (tid & 1) * 16;
    u32 sA = (u32)__cvta_generic_to_shared(&As[0][0]);
    u32 sB0 = (u32)__cvta_generic_to_shared(&Bs[0][0][0]);
    u32 sB1 = (u32)__cvta_generic_to_shared(&Bs[1][0][0]);
    int arow = wm * 64 + (lane & 15);
    int brow = wn * 32 + (lane & 15);
    int csel = (lane >> 4) * 8;

    constexpr int T = NCB * 4;   // total k-stages across column blocks
    auto tilePtr = [&](int t) {
        int cb = t >> 2, s = t & 3;
        return Bw + (size_t)(cb * 128 + ldRow) * 128 + s * 32 + ldCol;
    };

    uint4 bv0, bv1;
    {   const __nv_bfloat16* p = tilePtr(0);
        bv0 = *(const uint4*)p; bv1 = *(const uint4*)(p + 8); }
    // stage 0 into buffer 0
    *(uint4*)&Bs[0][ldRow][ldCol]     = bv0;
    *(uint4*)&Bs[0][ldRow][ldCol + 8] = bv1;
    {   const __nv_bfloat16* p = tilePtr(1);
        bv0 = *(const uint4*)p; bv1 = *(const uint4*)(p + 8); }
    __syncthreads();

    float acc[4][4][4];
#pragma unroll
    for (int t = 0; t < T; t++) {
        int s = t & 3;
        if (s == 0) {
#pragma unroll
            for (int i = 0; i < 4; i++)
#pragma unroll
                for (int j = 0; j < 4; j++)
#pragma unroll
                    for (int r = 0; r < 4; r++) acc[i][j][r] = 0.f;
        }
        // stage t+1 into the other buffer; prefetch t+2
        if (t + 1 < T) {
            __nv_bfloat16* dst = &Bs[(t + 1) & 1][ldRow][ldCol];
            *(uint4*)dst       = bv0;
            *(uint4*)(dst + 8) = bv1;
            if (t + 2 < T) {
                const __nv_bfloat16* p = tilePtr(t + 2);
                bv0 = *(const uint4*)p; bv1 = *(const uint4*)(p + 8);
            }
        }
        // compute on buffer t&1
        u32 sB = (t & 1) ? sB1 : sB0;
#pragma unroll
        for (int kk2 = 0; kk2 < 2; kk2++) {
            int acol = s * 32 + kk2 * 16 + csel;
            int bcol = kk2 * 16 + csel;
            u32 af[4][4], bf[4][2];
#pragma unroll
            for (int mi = 0; mi < 4; mi++) {
                u32 addr = sA + (u32)(((arow + mi * 16) * ASTR + acol) * 2);
                ldsm_x4(af[mi][0], af[mi][1], af[mi][2], af[mi][3], addr);
            }
#pragma unroll
            for (int np = 0; np < 2; np++) {
                u32 r0, r1, r2, r3;
                u32 addr = sB + (u32)(((brow + np * 16) * LDS_S + bcol) * 2);
                ldsm_x4(r0, r1, r2, r3, addr);
                bf[np * 2][0]     = r0; bf[np * 2][1]     = r2;
                bf[np * 2 + 1][0] = r1; bf[np * 2 + 1][1] = r3;
            }
#pragma unroll
            for (int mi = 0; mi < 4; mi++)
#pragma unroll
                for (int nj = 0; nj < 4; nj++)
                    mma_bf16(acc[mi][nj], af[mi], bf[nj]);
        }
        if (s == 3) {   // epilogue for this column block
            int colBase = (t >> 2) * 128;
#pragma unroll
            for (int mi = 0; mi < 4; mi++)
#pragma unroll
                for (int rp = 0; rp < 2; rp++) {
                    size_t r = rowBase + wm * 64 + mi * 16 + rp * 8 + (lane >> 2);
#pragma unroll
                    for (int nj = 0; nj < 4; nj++) {
                        int cgl = colBase + wn * 32 + nj * 8 + (lane & 3) * 2;
                        epi.store(r, cgl, make_float2(acc[mi][nj][rp * 2],
                                                      acc[mi][nj][rp * 2 + 1]));
                    }
                }
        }
        __syncthreads();
    }
}

// =================================================================
// bf16 GEMM, A & B double-buffered, ONE barrier per stage — proj
// =================================================================
template <class Epi>
__global__ __launch_bounds__(256, 2) void bgemm_kernel(
    const __nv_bfloat16* __restrict__ A, const __nv_bfloat16* __restrict__ Bw,
    int K, Epi epi)
{
    __shared__ __nv_bfloat16 As[2][128][LDS_S];
    __shared__ __nv_bfloat16 Bs[2][128][LDS_S];
    int tid = threadIdx.x, lane = tid & 31, w = tid >> 5;
    int wm = w & 1, wn = w >> 1;
    size_t rowBase = (size_t)blockIdx.y * 128;
    int    colBase = blockIdx.x * 128;

    int ldRow = tid >> 1;
    int ldCol = (tid & 1) * 16;
    const __nv_bfloat16* Ap = A  + (rowBase + ldRow) * K + ldCol;
    const __nv_bfloat16* Bp = Bw + (size_t)(colBase + ldRow) * K + ldCol;

    float acc[4][4][4];
#pragma unroll
    for (int i = 0; i < 4; i++)
#pragma unroll
        for (int j = 0; j < 4; j++)
#pragma unroll
            for (int r = 0; r < 4; r++) acc[i][j][r] = 0.f;

    uint4 av0 = *(const uint4*)Ap, av1 = *(const uint4*)(Ap + 8);
    uint4 bv0 = *(const uint4*)Bp, bv1 = *(const uint4*)(Bp + 8);
    *(uint4*)&As[0][ldRow][ldCol]     = av0;
    *(uint4*)&As[0][ldRow][ldCol + 8] = av1;
    *(uint4*)&Bs[0][ldRow][ldCol]     = bv0;
    *(uint4*)&Bs[0][ldRow][ldCol + 8] = bv1;
    if (K > 32) {
        Ap += 32; Bp += 32;
        av0 = *(const uint4*)Ap; av1 = *(const uint4*)(Ap + 8);
        bv0 = *(const uint4*)Bp; bv1 = *(const uint4*)(Bp + 8);
    }
    __syncthreads();

    u32 sA0 = (u32)__cvta_generic_to_shared(&As[0][0][0]);
    u32 sA1 = (u32)__cvta_generic_to_shared(&As[1][0][0]);
    u32 sB0 = (u32)__cvta_generic_to_shared(&Bs[0][0][0]);
    u32 sB1 = (u32)__cvta_generic_to_shared(&Bs[1][0][0]);
    int arow = wm * 64 + (lane & 15);
    int brow = wn * 32 + (lane & 15);
    int csel = (lane >> 4) * 8;

    int S = K >> 5;
    for (int t = 0; t < S; t++) {
        if (t + 1 < S) {
            __nv_bfloat16* da = &As[(t + 1) & 1][ldRow][ldCol];
            __nv_bfloat16* db = &Bs[(t + 1) & 1][ldRow][ldCol];
            *(uint4*)da = av0; *(uint4*)(da + 8) = av1;
            *(uint4*)db = bv0; *(uint4*)(db + 8) = bv1;
            if (t + 2 < S) {
                Ap += 32; Bp += 32;
                av0 = *(const uint4*)Ap; av1 = *(const uint4*)(Ap + 8);
                bv0 = *(const uint4*)Bp; bv1 = *(const uint4*)(Bp + 8);
            }
        }
        u32 sA = (t & 1) ? sA1 : sA0;
        u32 sB = (t & 1) ? sB1 : sB0;
#pragma unroll
        for (int kk = 0; kk < 32; kk += 16) {
            u32 af[4][4], bf[4][2];
            int acol = kk + csel;
#pragma unroll
            for (int mi = 0; mi < 4; mi++) {
                u32 addr = sA + (u32)(((arow + mi * 16) * LDS_S + acol) * 2);
                ldsm_x4(af[mi][0], af[mi][1], af[mi][2], af[mi][3], addr);
            }
#pragma unroll
            for (int np = 0; np < 2; np++) {
                u32 r0, r1, r2, r3;
                u32 addr = sB + (u32)(((brow + np * 16) * LDS_S + acol) * 2);
                ldsm_x4(r0, r1, r2, r3, addr);
                bf[np * 2][0]     = r0; bf[np * 2][1]     = r2;
                bf[np * 2 + 1][0] = r1; bf[np * 2 + 1][1] = r3;
            }
#pragma unroll
            for (int mi = 0; mi < 4; mi++)
#pragma unroll
                for (int nj = 0; nj < 4; nj++)
                    mma_bf16(acc[mi][nj], af[mi], bf[nj]);
        }
        __syncthreads();
    }

#pragma unroll
    for (int mi = 0; mi < 4; mi++)
#pragma unroll
        for (int rp = 0; rp < 2; rp++) {
            size_t r = rowBase + wm * 64 + mi * 16 + rp * 8 + (lane >> 2);
#pragma unroll
            for (int nj = 0; nj < 4; nj++) {
                int cgl = colBase + wn * 32 + nj * 8 + (lane & 3) * 2;
                epi.store(r, cgl, make_float2(acc[mi][nj][rp * 2],
                                              acc[mi][nj][rp * 2 + 1]));
            }
        }
}

// =================================================================
// FC2 GEMM (K=512, double-buffered) + bias + ls2 + residual +
// TRANSPOSED store to d_out (B,C,P). grid (1, M/128).
// =================================================================
__global__ __launch_bounds__(256, 2) void bgemm_fc2_tr_kernel(
    const __nv_bfloat16* __restrict__ A, const __nv_bfloat16* __restrict__ Bw,
    const float* __restrict__ bias, const float* __restrict__ ls,
    const float* __restrict__ resid, float* __restrict__ out)
{
    __shared__ __nv_bfloat16 As[2][128][LDS_S];
    __shared__ __nv_bfloat16 Bs[2][128][LDS_S];
    __shared__ float tsm[32][132];
    constexpr int K = 512;
    constexpr int S = K >> 5;
    int tid = threadIdx.x, lane = tid & 31, w = tid >> 5;
    int wm = w & 1, wn = w >> 1;
    size_t rowBase = (size_t)blockIdx.y * 128;

    int ldRow = tid >> 1;
    int ldCol = (tid & 1) * 16;
    const __nv_bfloat16* Ap = A  + (rowBase + ldRow) * K + ldCol;
    const __nv_bfloat16* Bp = Bw + (size_t)ldRow * K + ldCol;

    float acc[4][4][4];
#pragma unroll
    for (int i = 0; i < 4; i++)
#pragma unroll
        for (int j = 0; j < 4; j++)
#pragma unroll
            for (int r = 0; r < 4; r++) acc[i][j][r] = 0.f;

    uint4 av0 = *(const uint4*)Ap, av1 = *(const uint4*)(Ap + 8);
    uint4 bv0 = *(const uint4*)Bp, bv1 = *(const uint4*)(Bp + 8);
    *(uint4*)&As[0][ldRow][ldCol]     = av0;
    *(uint4*)&As[0][ldRow][ldCol + 8] = av1;
    *(uint4*)&Bs[0][ldRow][ldCol]     = bv0;
    *(uint4*)&Bs[0][ldRow][ldCol + 8] = bv1;
    Ap += 32; Bp += 32;
    av0 = *(const uint4*)Ap; av1 = *(const uint4*)(Ap + 8);
    bv0 = *(const uint4*)Bp; bv1 = *(const uint4*)(Bp + 8);
    __syncthreads();

    u32 sA0 = (u32)__cvta_generic_to_shared(&As[0][0][0]);
    u32 sA1 = (u32)__cvta_generic_to_shared(&As[1][0][0]);
    u32 sB0 = (u32)__cvta_generic_to_shared(&Bs[0][0][0]);
    u32 sB1 = (u32)__cvta_generic_to_shared(&Bs[1][0][0]);
    int arow = wm * 64 + (lane & 15);
    int brow = wn * 32 + (lane & 15);
    int csel = (lane >> 4) * 8;

    for (int t = 0; t < S; t++) {
        if (t + 1 < S) {
            __nv_bfloat16* da = &As[(t + 1) & 1][ldRow][ldCol];
            __nv_bfloat16* db = &Bs[(t + 1) & 1][ldRow][ldCol];
            *(uint4*)da = av0; *(uint4*)(da + 8) = av1;
            *(uint4*)db = bv0; *(uint4*)(db + 8) = bv1;
            if (t + 2 < S) {
                Ap += 32; Bp += 32;
                av0 = *(const uint4*)Ap; av1 = *(const uint4*)(Ap + 8);
                bv0 = *(const uint4*)Bp; bv1 = *(const uint4*)(Bp + 8);
            }
        }
        u32 sA = (t & 1) ? sA1 : sA0;
        u32 sB = (t & 1) ? sB1 : sB0;
#pragma unroll
        for (int kk = 0; kk < 32; kk += 16) {
            u32 af[4][4], bf[4][2];
            int acol = kk + csel;
#pragma unroll
            for (int mi = 0; mi < 4; mi++) {
                u32 addr = sA + (u32)(((arow + mi * 16) * LDS_S + acol) * 2);
                ldsm_x4(af[mi][0], af[mi][1], af[mi][2], af[mi][3], addr);
            }
#pragma unroll
            for (int np = 0; np < 2; np++) {
                u32 r0, r1, r2, r3;
                u32 addr = sB + (u32)(((brow + np * 16) * LDS_S + acol) * 2);
                ldsm_x4(r0, r1, r2, r3, addr);
                bf[np * 2][0]     = r0; bf[np * 2][1]     = r2;
                bf[np * 2 + 1][0] = r1; bf[np * 2 + 1][1] = r3;
            }
#pragma unroll
            for (int mi = 0; mi < 4; mi++)
#pragma unroll
                for (int nj = 0; nj < 4; nj++)
                    mma_bf16(acc[mi][nj], af[mi], bf[nj]);
        }
        __syncthreads();
    }

    // epilogue: bias + ls + residual, then transposed write via smem
    int b  = (int)(rowBase / P);
    int p0 = (int)(rowBase % P);
#pragma unroll
    for (int cg = 0; cg < 4; cg++) {
        __syncthreads();
        if (wn == cg) {
#pragma unroll
            for (int mi = 0; mi < 4; mi++)
#pragma unroll
                for (int rp = 0; rp < 2; rp++) {
                    int pl = wm * 64 + mi * 16 + rp * 8 + (lane >> 2);
                    size_t grow = rowBase + pl;
#pragma unroll
                    for (int nj = 0; nj < 4; nj++) {
                        int cl = nj * 8 + (lane & 3) * 2;
                        int cglob = cg * 32 + cl;
                        float2 bb = *(const float2*)(bias + cglob);
                        float2 ss = *(const float2*)(ls + cglob);
                        float2 rr = *(const float2*)(resid + grow * 128 + cglob);
                        tsm[cl][pl]     = rr.x + ss.x * (acc[mi][nj][rp*2]   + bb.x);
                        tsm[cl + 1][pl] = rr.y + ss.y * (acc[mi][nj][rp*2+1] + bb.y);
                    }
                }
        }
        __syncthreads();
        int c  = tid >> 3;
        int pj = (tid & 7) * 16;
        float* dst = out + (size_t)b * C * P + (size_t)(cg * 32 + c) * P + p0 + pj;
        const float* srcp = &tsm[c][pj];
#pragma unroll
        for (int j = 0; j < 4; j++)
            *(float4*)(dst + j * 4) = *(const float4*)(srcp + j * 4);
    }
}

// =================================================================
// Warp-level attention core (unchanged)
// =================================================================
constexpr int AST = 24;

__device__ __forceinline__ void attn_warp(
    const __nv_bfloat16* Qs, const __nv_bfloat16* Ks, const __nv_bfloat16* Vs,
    int nchunks, int lane, float o[2][2][4], float rsum[2][2])
{
    const float scale = 0.25f;
    int g = lane >> 3, i = lane & 7;
    int r4 = lane >> 2, c4 = lane & 3;

    u32 aq[2][4];
#pragma unroll
    for (int mt = 0; mt < 2; mt++) {
        u32 addr = (u32)__cvta_generic_to_shared(
            Qs + (mt * 16 + (g & 1) * 8 + i) * AST + (g >> 1) * 8);
        ldsm_x4(aq[mt][0], aq[mt][1], aq[mt][2], aq[mt][3], addr);
    }

#pragma unroll
    for (int mt = 0; mt < 2; mt++)
#pragma unroll
        for (int nh = 0; nh < 2; nh++)
#pragma unroll
            for (int q = 0; q < 4; q++) o[mt][nh][q] = 0.f;
    rsum[0][0] = rsum[0][1] = rsum[1][0] = rsum[1][1] = 0.f;

    for (int ch = 0; ch < nchunks; ch++) {
        const __nv_bfloat16* Kc = Ks + ch * 64 * AST;
        const __nv_bfloat16* Vc = Vs + ch * 64 * AST;
        u32 pf[2][4][4];
#pragma unroll
        for (int nt = 0; nt < 8; nt++) {
            const __nv_bfloat16* kp = Kc + (nt * 8 + r4) * AST + c4 * 2;
            u32 bb[2];
            bb[0] = *(const u32*)kp;
            bb[1] = *(const u32*)(kp + 8);
            float s0[4] = {0.f, 0.f, 0.f, 0.f};
            float s1[4] = {0.f, 0.f, 0.f, 0.f};
            mma_bf16(s0, aq[0], bb);
            mma_bf16(s1, aq[1], bb);
            float e00 = __expf(s0[0] * scale), e01 = __expf(s0[1] * scale);
            float e02 = __expf(s0[2] * scale), e03 = __expf(s0[3] * scale);
            float e10 = __expf(s1[0] * scale), e11 = __expf(s1[1] * scale);
            float e12 = __expf(s1[2] * scale), e13 = __expf(s1[3] * scale);
            rsum[0][0] += e00 + e01;  rsum[0][1] += e02 + e03;
            rsum[1][0] += e10 + e11;  rsum[1][1] += e12 + e13;
            int kt = nt >> 1, lo = (nt & 1) * 2;
            pf[0][kt][lo + 0] = pack_bf16x2(e00, e01);
            pf[0][kt][lo + 1] = pack_bf16x2(e02, e03);
            pf[1][kt][lo + 0] = pack_bf16x2(e10, e11);
            pf[1][kt][lo + 1] = pack_bf16x2(e12, e13);
        }
#pragma unroll
        for (int kt = 0; kt < 4; kt++) {
            u32 v0, v1, v2, v3;
            u32 addr = (u32)__cvta_generic_to_shared(
                Vc + (kt * 16 + (g & 1) * 8 + i) * AST + (g >> 1) * 8);
            ldsm_x4_t(v0, v1, v2, v3, addr);
            u32 b0[2] = {v0, v1};
            u32 b1[2] = {v2, v3};
            mma_bf16(o[0][0], pf[0][kt], b0);
            mma_bf16(o[0][1], pf[0][kt], b1);
            mma_bf16(o[1][0], pf[1][kt], b0);
            mma_bf16(o[1][1], pf[1][kt], b1);
        }
    }

#pragma unroll
    for (int mt = 0; mt < 2; mt++)
#pragma unroll
        for (int hh = 0; hh < 2; hh++) {
            float v = rsum[mt][hh];
            v += __shfl_xor_sync(0xffffffffu, v, 1);
            v += __shfl_xor_sync(0xffffffffu, v, 2);
            rsum[mt][hh] = v;
        }
}

// =================================================================
// Window attention: CTA per (b, wy, wx); 4 heads x 2 warps.
// =================================================================
__global__ __launch_bounds__(256) void win_attn_kernel(
    const __nv_bfloat16* __restrict__ qkv, __nv_bfloat16* __restrict__ abuf)
{
    __shared__ __align__(16) __nv_bfloat16 Qs[4 * 64 * AST];
    __shared__ __align__(16) __nv_bfloat16 Ks[4 * 64 * AST];
    __shared__ __align__(16) __nv_bfloat16 Vs[4 * 64 * AST];

    int blk = blockIdx.x;
    int b  = blk >> 8;
    int wy = (blk >> 4) & 15;
    int wx = blk & 15;
    int tid = threadIdx.x;

    {
        int h = tid >> 6, t = tid & 63;
        int y = t >> 3, x = t & 7;
        size_t p = (size_t)(wy * 8 + y) * WW + wx * 8 + x;
        const __nv_bfloat16* base = qkv + ((size_t)b * P + p) * 384 + h * 16;
        int row = (h * 64 + t) * AST;
        const uint4* q4 = (const uint4*)base;
        const uint4* k4 = (const uint4*)(base + 128);
        const uint4* v4 = (const uint4*)(base + 256);
        *(uint4*)&Qs[row] = q4[0];  *(uint4*)&Qs[row + 8] = q4[1];
        *(uint4*)&Ks[row] = k4[0];  *(uint4*)&Ks[row + 8] = k4[1];
        *(uint4*)&Vs[row] = v4[0];  *(uint4*)&Vs[row + 8] = v4[1];
    }
    __syncthreads();

    int w = tid >> 5, lane = tid & 31;
    int h = w >> 1;
    int qb = (w & 1) * 32;

    float o[2][2][4], rsum[2][2];
    attn_warp(Qs + (h * 64 + qb) * AST, Ks + h * 64 * AST, Vs + h * 64 * AST,
              1, lane, o, rsum);

    int r4 = lane >> 2, c4 = lane & 3;
#pragma unroll
    for (int mt = 0; mt < 2; mt++) {
        float inv0 = 1.f / rsum[mt][0];
        float inv1 = 1.f / rsum[mt][1];
#pragma unroll
        for (int hh = 0; hh < 2; hh++) {
            int q = qb + mt * 16 + hh * 8 + r4;
            size_t p = (size_t)(wy * 8 + (q >> 3)) * WW + wx * 8 + (q & 7);
            float inv = hh ? inv1 : inv0;
            __nv_bfloat16* ob = abuf + ((size_t)b * P + p) * C + h * 16;
#pragma unroll
            for (int nh = 0; nh < 2; nh++) {
                float ox = o[mt][nh][hh * 2]     * inv;
                float oy = o[mt][nh][hh * 2 + 1] * inv;
                *(__nv_bfloat162*)(ob + nh * 8 + c4 * 2) = __floats2bfloat162_rn(ox, oy);
            }
        }
    }
}

// =================================================================
// Grid attention: CTA per (b, pos-in-window, head); 8 warps x 32 q.
// =================================================================
__global__ __launch_bounds__(256) void grid_attn_kernel(
    const __nv_bfloat16* __restrict__ qkv, __nv_bfloat16* __restrict__ abuf)
{
    __shared__ __align__(16) __nv_bfloat16 Qs[256 * AST];
    __shared__ __align__(16) __nv_bfloat16 Ks[256 * AST];
    __shared__ __align__(16) __nv_bfloat16 Vs[256 * AST];

    int blk = blockIdx.x;
    int b   = blk >> 8;
    int pos = (blk >> 2) & 63;
    int hg  = blk & 3;
    int y = pos >> 3, x = pos & 7;
    int tid = threadIdx.x;

    {
        int j = tid;
        int wy = j >> 4, wx = j & 15;
        size_t p = (size_t)(wy * 8 + y) * WW + wx * 8 + x;
        const __nv_bfloat16* base = qkv + ((size_t)b * P + p) * 384 + 64 + hg * 16;
        int row = j * AST;
        const uint4* q4 = (const uint4*)base;
        const uint4* k4 = (const uint4*)(base + 128);
        const uint4* v4 = (const uint4*)(base + 256);
        *(uint4*)&Qs[row] = q4[0];  *(uint4*)&Qs[row + 8] = q4[1];
        *(uint4*)&Ks[row] = k4[0];  *(uint4*)&Ks[row + 8] = k4[1];
        *(uint4*)&Vs[row] = v4[0];  *(uint4*)&Vs[row + 8] = v4[1];
    }
    __syncthreads();

    int w = tid >> 5, lane = tid & 31;
    int qb = w * 32;

    float o[2][2][4], rsum[2][2];
    attn_warp(Qs + qb * AST, Ks, Vs, 4, lane, o, rsum);

    int r4 = lane >> 2, c4 = lane & 3;
#pragma unroll
    for (int mt = 0; mt < 2; mt++) {
        float inv0 = 1.f / rsum[mt][0];
        float inv1 = 1.f / rsum[mt][1];
#pragma unroll
        for (int hh = 0; hh < 2; hh++) {
            int j = qb + mt * 16 + hh * 8 + r4;
            int wy = j >> 4, wx = j & 15;
            size_t p = (size_t)(wy * 8 + y) * WW + wx * 8 + x;
            float inv = hh ? inv1 : inv0;
            __nv_bfloat16* ob = abuf + ((size_t)b * P + p) * C + 64 + hg * 16;
#pragma unroll
            for (int nh = 0; nh < 2; nh++) {
                float ox = o[mt][nh][hh * 2]     * inv;
                float oy = o[mt][nh][hh * 2 + 1] * inv;
                *(__nv_bfloat162*)(ob + nh * 8 + c4 * 2) = __floats2bfloat162_rn(ox, oy);
            }
        }
    }
}

// =================================================================
// host launcher
// =================================================================
extern "C" void kernel_launch(void* const* d_in, const int* in_sizes, int n_in,
                              void* d_out, int out_size)
{
    const float* x       = (const float*)d_in[0];
    const float* conv_w  = (const float*)d_in[1];
    const float* conv_b  = (const float*)d_in[2];
    const float* norm1_w = (const float*)d_in[3];
    const float* norm1_b = (const float*)d_in[4];
    const float* wqkv    = (const float*)d_in[5];
    const float* proj_w  = (const float*)d_in[6];
    const float* proj_b  = (const float*)d_in[7];
    const float* norm2_w = (const float*)d_in[8];
    const float* norm2_b = (const float*)d_in[9];
    const float* fc1_w   = (const float*)d_in[10];
    const float* fc1_b   = (const float*)d_in[11];
    const float* fc2_w   = (const float*)d_in[12];
    const float* fc2_b   = (const float*)d_in[13];
    const float* ls1     = (const float*)d_in[14];
    const float* ls2     = (const float*)d_in[15];
    float* out = (float*)d_out;

    float *pxt, *pxt2;
    __nv_bfloat16 *pqkv, *pabuf, *ph, *pwq, *pwp, *pw1, *pw2;
    cudaGetSymbolAddress((void**)&pxt,   g_xt);
    cudaGetSymbolAddress((void**)&pqkv,  g_qkvb);
    cudaGetSymbolAddress((void**)&pabuf, g_abuf);
    cudaGetSymbolAddress((void**)&pxt2,  g_xt2);
    cudaGetSymbolAddress((void**)&ph,    g_h);
    cudaGetSymbolAddress((void**)&pwq,   g_wqkv_t);
    cudaGetSymbolAddress((void**)&pwp,   g_proj_t);
    cudaGetSymbolAddress((void**)&pw1,   g_fc1_t);
    cudaGetSymbolAddress((void**)&pw2,   g_fc2_t);

    // 0. all weight transposes in one launch
    wt_all_kernel<<<192, dim3(32, 8)>>>(wqkv, proj_w, fc1_w, fc2_w,
                                        pwq, pwp, pw1, pw2);

    // 1. conv + residual + transpose -> xt (fp32)
    conv_kernel<<<dim3(16, HH, BS), 256>>>(x, conv_w, conv_b, pxt);

    // 2. LN1 + QKV GEMM fused (LN once, 3 column blocks in-kernel)
    {
        EpiQKVb e{pqkv};
        lngemm_kernel<3, EpiQKVb><<<(unsigned)(M / 128), 256>>>(
            pxt, norm1_w, norm1_b, pwq, e);
    }

    // 3. attention (tensor-core) -> abuf (bf16)
    win_attn_kernel <<<BS * 256, 256>>>(pqkv, pabuf);
    grid_attn_kernel<<<BS * 256, 256>>>(pqkv, pabuf);

    // 4. proj GEMM + ls1 + residual -> xt2 (fp32)
    {
        EpiProj e{proj_b, ls1, pxt, pxt2};
        bgemm_kernel<EpiProj><<<dim3(1, (unsigned)(M / 128)), 256>>>(pabuf, pwp, 128, e);
    }

    // 5. LN2 + FC1 GEMM fused (LN once, 4 column blocks in-kernel)
    {
        EpiGelu e{fc1_b, ph};
        lngemm_kernel<4, EpiGelu><<<(unsigned)(M / 128), 256>>>(
            pxt2, norm2_w, norm2_b, pw1, e);
    }

    // 6. FC2 + bias + ls2 + residual + transposed store -> d_out
    bgemm_fc2_tr_kernel<<<dim3(1, (unsigned)(M / 128)), 256>>>(
        ph, pw2, fc2_b, ls2, pxt2, out);

    (void)in_sizes; (void)n_in; (void)out_size;
}

// round 12
// speedup vs baseline: 1.2190x; 1.0180x over previous
#include <cuda_runtime.h>
#include <cuda_bf16.h>
#include <math.h>
#include <stdint.h>
#include <string.h>

typedef unsigned int u32;

// ---------------- problem constants ----------------
constexpr int BS  = 8;
constexpr int C   = 128;
constexpr int HH  = 128;
constexpr int WW  = 128;
constexpr int P   = HH * WW;
constexpr long long M = (long long)BS * P;  // 131072 rows
constexpr int HID = 512;

// ---------------- device scratch ----------------
__device__ float          g_xt  [(size_t)M * C];
__device__ __nv_bfloat16  g_qkvb[(size_t)M * 3 * C];
__device__ __nv_bfloat16  g_abuf[(size_t)M * C];
__device__ float          g_xt2 [(size_t)M * C];
__device__ __nv_bfloat16  g_h   [(size_t)M * HID];

// transposed bf16 weights [N][K]
__device__ __nv_bfloat16  g_wqkv_t[384 * 128];
__device__ __nv_bfloat16  g_proj_t[128 * 128];
__device__ __nv_bfloat16  g_fc1_t [512 * 128];
__device__ __nv_bfloat16  g_fc2_t [128 * 512];

// =================================================================
// primitives
// =================================================================
__device__ __forceinline__ void ldsm_x4(u32 &r0, u32 &r1, u32 &r2, u32 &r3, u32 addr)
{
    asm volatile("ldmatrix.sync.aligned.m8n8.x4.shared.b16 {%0,%1,%2,%3}, [%4];"
                 : "=r"(r0), "=r"(r1), "=r"(r2), "=r"(r3) : "r"(addr));
}
__device__ __forceinline__ void ldsm_x4_t(u32 &r0, u32 &r1, u32 &r2, u32 &r3, u32 addr)
{
    asm volatile("ldmatrix.sync.aligned.m8n8.x4.trans.shared.b16 {%0,%1,%2,%3}, [%4];"
                 : "=r"(r0), "=r"(r1), "=r"(r2), "=r"(r3) : "r"(addr));
}
__device__ __forceinline__ void mma_bf16(float* d, const u32* a, const u32* b)
{
    asm volatile("mma.sync.aligned.m16n8k16.row.col.f32.bf16.bf16.f32 "
                 "{%0,%1,%2,%3}, {%4,%5,%6,%7}, {%8,%9}, {%0,%1,%2,%3};"
                 : "+f"(d[0]), "+f"(d[1]), "+f"(d[2]), "+f"(d[3])
                 : "r"(a[0]), "r"(a[1]), "r"(a[2]), "r"(a[3]),
                   "r"(b[0]), "r"(b[1]));
}
__device__ __forceinline__ u32 pack_bf16x2(float a, float b)
{
    __nv_bfloat162 t = __floats2bfloat162_rn(a, b);
    u32 r;
    memcpy(&r, &t, 4);
    return r;
}
__device__ __forceinline__ void cp16(u32 dst, const void* src)
{
    asm volatile("cp.async.cg.shared.global [%0], [%1], 16;" :: "r"(dst), "l"(src));
}
__device__ __forceinline__ void cp_commit()
{
    asm volatile("cp.async.commit_group;");
}
template <int N>
__device__ __forceinline__ void cp_wait()
{
    asm volatile("cp.async.wait_group %0;" :: "n"(N));
}

// =================================================================
// merged weight transpose + bf16 convert
// =================================================================
__global__ void wt_all_kernel(const float* __restrict__ wqkv, const float* __restrict__ projw,
                              const float* __restrict__ fc1w, const float* __restrict__ fc2w,
                              __nv_bfloat16* oq, __nv_bfloat16* op,
                              __nv_bfloat16* o1, __nv_bfloat16* o2)
{
    __shared__ float t[32][33];
    int id = blockIdx.x;
    const float* W; __nv_bfloat16* Wt; int K, N, local;
    if (id < 48)       { W = wqkv;  Wt = oq; K = 128; N = 384; local = id; }
    else if (id < 64)  { W = projw; Wt = op; K = 128; N = 128; local = id - 48; }
    else if (id < 128) { W = fc1w;  Wt = o1; K = 128; N = 512; local = id - 64; }
    else               { W = fc2w;  Wt = o2; K = 512; N = 128; local = id - 128; }
    int nTiles = N / 32;
    int n0 = (local % nTiles) * 32;
    int k0 = (local / nTiles) * 32;
    int tx = threadIdx.x, ty = threadIdx.y;
    for (int i = ty; i < 32; i += 8)
        t[i][tx] = W[(size_t)(k0 + i) * N + n0 + tx];
    __syncthreads();
    for (int i = ty; i < 32; i += 8)
        Wt[(size_t)(n0 + i) * K + k0 + tx] = __float2bfloat16(t[tx][i]);
}

// =================================================================
// depthwise 3x3 conv + bias + residual -> xt (B,P,C)
// =================================================================
__global__ __launch_bounds__(256) void conv_kernel(
    const float* __restrict__ x, const float* __restrict__ cw,
    const float* __restrict__ cb, float* __restrict__ xt)
{
    int b  = blockIdx.z;
    int h  = blockIdx.y;
    int c0 = (blockIdx.x >> 2) * 32;
    int w0 = (blockIdx.x & 3) * 32;
    __shared__ float sx[32][3][36];
    __shared__ float so[32][33];
    int tid = threadIdx.x;

    for (int i = tid; i < 32 * 3 * 34; i += 256) {
        int c  = i / (3 * 34);
        int r  = (i / 34) % 3;
        int wi = i % 34;
        int hh = h + r - 1;
        int wg = w0 + wi - 1;
        float v = 0.f;
        if (hh >= 0 && hh < HH && wg >= 0 && wg < WW)
            v = x[(((size_t)b * C + c0 + c) * HH + hh) * WW + wg];
        sx[c][r][wi] = v;
    }
    __syncthreads();

    int c     = tid >> 3;
    int wbase = (tid & 7) * 4;
    const float* wg9 = cw + (size_t)(c0 + c) * 9;
    float w00 = wg9[0], w01 = wg9[1], w02 = wg9[2];
    float w10 = wg9[3], w11 = wg9[4], w12 = wg9[5];
    float w20 = wg9[6], w21 = wg9[7], w22 = wg9[8];
    float bias = cb[c0 + c];
#pragma unroll
    for (int j = 0; j < 4; j++) {
        int wi = wbase + j;
        float acc = sx[c][0][wi] * w00 + sx[c][0][wi+1] * w01 + sx[c][0][wi+2] * w02
                  + sx[c][1][wi] * w10 + sx[c][1][wi+1] * w11 + sx[c][1][wi+2] * w12
                  + sx[c][2][wi] * w20 + sx[c][2][wi+1] * w21 + sx[c][2][wi+2] * w22;
        so[c][wi] = acc + bias + sx[c][1][wi+1];
    }
    __syncthreads();

    int cc = tid & 31;
    for (int wr = tid >> 5; wr < 32; wr += 8) {
        xt[((size_t)b * P + (size_t)h * WW + w0 + wr) * C + c0 + cc] = so[cc][wr];
    }
}

// =================================================================
// Epilogue functors
// =================================================================
struct EpiQKVb {
    __nv_bfloat16* out;
    __device__ __forceinline__ void store(size_t row, int col, float2 v) const {
        *(__nv_bfloat162*)(out + row * 384 + col) = __floats2bfloat162_rn(v.x, v.y);
    }
};
struct EpiProj {
    const float* bias; const float* ls; const float* resid; float* out;
    __device__ __forceinline__ void store(size_t row, int col, float2 v) const {
        float2 bb = *(const float2*)(bias + col);
        float2 ss = *(const float2*)(ls + col);
        float2 rr = *(const float2*)(resid + row * 128 + col);
        float2 o;
        o.x = rr.x + ss.x * (v.x + bb.x);
        o.y = rr.y + ss.y * (v.y + bb.y);
        *(float2*)(out + row * 128 + col) = o;
    }
};
struct EpiGelu {
    const float* bias; __nv_bfloat16* out;
    __device__ __forceinline__ float gelu(float g) const {
        return 0.5f * g * (1.f + erff(g * 0.70710678118654752f));
    }
    __device__ __forceinline__ void store(size_t row, int col, float2 v) const {
        float2 bb = *(const float2*)(bias + col);
        *(__nv_bfloat162*)(out + row * 512 + col) =
            __floats2bfloat162_rn(gelu(v.x + bb.x), gelu(v.y + bb.y));
    }
};

// =================================================================
// Fused LN + GEMM, K=128, BK=64, B via 3-stage cp.async.
// grid (M/128), 256 thr. LN once; A resident.
// =================================================================
constexpr int ASTR = 136;
constexpr int BST64 = 72;    // BK=64 tile row stride
constexpr int LDS_S = 40;    // BK=32 tile row stride

template <int NCB, class Epi>
__global__ __launch_bounds__(256, 2) void lngemm_kernel(
    const float* __restrict__ A, const float* __restrict__ lnw,
    const float* __restrict__ lnb, const __nv_bfloat16* __restrict__ Bw,
    Epi epi)
{
    __shared__ __align__(16) __nv_bfloat16 As[128][ASTR];
    __shared__ __align__(16) __nv_bfloat16 Bs[3][128][BST64];
    int tid = threadIdx.x, lane = tid & 31, w = tid >> 5;
    int wm = w & 1, wn = w >> 1;
    size_t rowBase = (size_t)blockIdx.x * 128;

    int ldRow = tid >> 1, ldHalf = tid & 1;
    u32 sBbase = (u32)__cvta_generic_to_shared(&Bs[0][0][0]);
    constexpr u32 SLOT = 128 * BST64 * 2;
    constexpr int S = NCB * 2;

    auto issueB = [&](int t, int slot) {
        int cb = t >> 1, s = t & 1;
        const __nv_bfloat16* src = Bw + (size_t)(cb * 128 + ldRow) * 128
                                      + s * 64 + ldHalf * 32;
        u32 dst = sBbase + slot * SLOT + (u32)((ldRow * BST64 + ldHalf * 32) * 2);
#pragma unroll
        for (int j = 0; j < 4; j++) cp16(dst + j * 16, src + j * 8);
    };

    issueB(0, 0); cp_commit();
    issueB(1, 1); cp_commit();

    // ---- LN stage (once) ----
    {
        int row = tid >> 1, half = tid & 1;
        const float4* src = (const float4*)(A + (rowBase + row) * 128 + half * 64);
        float s = 0.f, q = 0.f;
#pragma unroll
        for (int i = 0; i < 16; i++) {
            float4 v = src[i];
            s += v.x + v.y + v.z + v.w;
            q += v.x*v.x + v.y*v.y + v.z*v.z + v.w*v.w;
        }
        s += __shfl_xor_sync(0xffffffffu, s, 1);
        q += __shfl_xor_sync(0xffffffffu, q, 1);
        float mean = s * (1.f / 128.f);
        float var  = q * (1.f / 128.f) - mean * mean;
        float rstd = rsqrtf(var + 1e-5f);
        const float4* wp = (const float4*)(lnw + half * 64);
        const float4* bp = (const float4*)(lnb + half * 64);
#pragma unroll
        for (int j = 0; j < 8; j++) {
            float4 a  = src[2*j],  b2  = src[2*j+1];
            float4 w4 = wp[2*j],   w42 = wp[2*j+1];
            float4 b4 = bp[2*j],   b42 = bp[2*j+1];
            u32 o[4];
            o[0] = pack_bf16x2((a.x-mean)*rstd*w4.x + b4.x,  (a.y-mean)*rstd*w4.y + b4.y);
            o[1] = pack_bf16x2((a.z-mean)*rstd*w4.z + b4.z,  (a.w-mean)*rstd*w4.w + b4.w);
            o[2] = pack_bf16x2((b2.x-mean)*rstd*w42.x + b42.x,(b2.y-mean)*rstd*w42.y + b42.y);
            o[3] = pack_bf16x2((b2.z-mean)*rstd*w42.z + b42.z,(b2.w-mean)*rstd*w42.w + b42.w);
            *(uint4*)&As[row][half * 64 + j * 8] = *(uint4*)o;
        }
    }

    u32 sA = (u32)__cvta_generic_to_shared(&As[0][0]);
    int arow = wm * 64 + (lane & 15);
    int brow = wn * 32 + (lane & 15);
    int csel = (lane >> 4) * 8;

    float acc[4][4][4];
#pragma unroll
    for (int t = 0; t < S; t++) {
        cp_wait<1>();
        __syncthreads();
        if (t + 2 < S) issueB(t + 2, (t + 2) % 3);
        cp_commit();

        if ((t & 1) == 0) {
#pragma unroll
            for (int i = 0; i < 4; i++)
#pragma unroll
                for (int j = 0; j < 4; j++)
#pragma unroll
                    for (int r = 0; r < 4; r++) acc[i][j][r] = 0.f;
        }
        u32 sB = sBbase + (u32)((t % 3) * SLOT);
#pragma unroll
        for (int kk = 0; kk < 4; kk++) {
            int acol = (t & 1) * 64 + kk * 16 + csel;
            int bcol = kk * 16 + csel;
            u32 af[4][4], bf[4][2];
#pragma unroll
            for (int mi = 0; mi < 4; mi++) {
                u32 addr = sA + (u32)(((arow + mi * 16) * ASTR + acol) * 2);
                ldsm_x4(af[mi][0], af[mi][1], af[mi][2], af[mi][3], addr);
            }
#pragma unroll
            for (int np = 0; np < 2; np++) {
                u32 r0, r1, r2, r3;
                u32 addr = sB + (u32)(((brow + np * 16) * BST64 + bcol) * 2);
                ldsm_x4(r0, r1, r2, r3, addr);
                bf[np * 2][0]     = r0; bf[np * 2][1]     = r2;
                bf[np * 2 + 1][0] = r1; bf[np * 2 + 1][1] = r3;
            }
#pragma unroll
            for (int mi = 0; mi < 4; mi++)
#pragma unroll
                for (int nj = 0; nj < 4; nj++)
                    mma_bf16(acc[mi][nj], af[mi], bf[nj]);
        }
        if ((t & 1) == 1) {
            int colBase = (t >> 1) * 128;
#pragma unroll
            for (int mi = 0; mi < 4; mi++)
#pragma unroll
                for (int rp = 0; rp < 2; rp++) {
                    size_t r = rowBase + wm * 64 + mi * 16 + rp * 8 + (lane >> 2);
#pragma unroll
                    for (int nj = 0; nj < 4; nj++) {
                        int cgl = colBase + wn * 32 + nj * 8 + (lane & 3) * 2;
                        epi.store(r, cgl, make_float2(acc[mi][nj][rp * 2],
                                                      acc[mi][nj][rp * 2 + 1]));
                    }
                }
        }
    }
}

// =================================================================
// streamed-A/B GEMM, BK=32, 4-stage cp.async — used for proj
// =================================================================
template <class Epi>
__global__ __launch_bounds__(256, 2) void bgemm_kernel(
    const __nv_bfloat16* __restrict__ A, const __nv_bfloat16* __restrict__ Bw,
    int K, Epi epi)
{
    __shared__ __align__(16) __nv_bfloat16 As[4][128][LDS_S];
    __shared__ __align__(16) __nv_bfloat16 Bs[4][128][LDS_S];
    int tid = threadIdx.x, lane = tid & 31, w = tid >> 5;
    int wm = w & 1, wn = w >> 1;
    size_t rowBase = (size_t)blockIdx.y * 128;
    int    colBase = blockIdx.x * 128;

    int ldRow = tid >> 1, ldHalf = tid & 1;
    u32 sAbase = (u32)__cvta_generic_to_shared(&As[0][0][0]);
    u32 sBbase = (u32)__cvta_generic_to_shared(&Bs[0][0][0]);
    constexpr u32 SLOT = 128 * LDS_S * 2;
    const __nv_bfloat16* Arow = A  + (rowBase + ldRow) * K + ldHalf * 16;
    const __nv_bfloat16* Brow = Bw + (size_t)(colBase + ldRow) * K + ldHalf * 16;
    u32 dstOff = (u32)((ldRow * LDS_S + ldHalf * 16) * 2);

    auto issue = [&](int t, int slot) {
        const __nv_bfloat16* sa = Arow + t * 32;
        const __nv_bfloat16* sb = Brow + t * 32;
        u32 da = sAbase + slot * SLOT + dstOff;
        u32 db = sBbase + slot * SLOT + dstOff;
        cp16(da, sa); cp16(da + 16, sa + 8);
        cp16(db, sb); cp16(db + 16, sb + 8);
    };

    int S = K >> 5;
    issue(0, 0); cp_commit();
    if (S > 1) issue(1, 1);
    cp_commit();
    if (S > 2) issue(2, 2);
    cp_commit();

    float acc[4][4][4];
#pragma unroll
    for (int i = 0; i < 4; i++)
#pragma unroll
        for (int j = 0; j < 4; j++)
#pragma unroll
            for (int r = 0; r < 4; r++) acc[i][j][r] = 0.f;

    int arow = wm * 64 + (lane & 15);
    int brow = wn * 32 + (lane & 15);
    int csel = (lane >> 4) * 8;

    for (int t = 0; t < S; t++) {
        cp_wait<2>();
        __syncthreads();
        if (t + 3 < S) issue(t + 3, (t + 3) & 3);
        cp_commit();

        u32 sA = sAbase + (u32)((t & 3) * SLOT);
        u32 sB = sBbase + (u32)((t & 3) * SLOT);
#pragma unroll
        for (int kk = 0; kk < 32; kk += 16) {
            u32 af[4][4], bf[4][2];
            int acol = kk + csel;
#pragma unroll
            for (int mi = 0; mi < 4; mi++) {
                u32 addr = sA + (u32)(((arow + mi * 16) * LDS_S + acol) * 2);
                ldsm_x4(af[mi][0], af[mi][1], af[mi][2], af[mi][3], addr);
            }
#pragma unroll
            for (int np = 0; np < 2; np++) {
                u32 r0, r1, r2, r3;
                u32 addr = sB + (u32)(((brow + np * 16) * LDS_S + acol) * 2);
                ldsm_x4(r0, r1, r2, r3, addr);
                bf[np * 2][0]     = r0; bf[np * 2][1]     = r2;
                bf[np * 2 + 1][0] = r1; bf[np * 2 + 1][1] = r3;
            }
#pragma unroll
            for (int mi = 0; mi < 4; mi++)
#pragma unroll
                for (int nj = 0; nj < 4; nj++)
                    mma_bf16(acc[mi][nj], af[mi], bf[nj]);
        }
    }

#pragma unroll
    for (int mi = 0; mi < 4; mi++)
#pragma unroll
        for (int rp = 0; rp < 2; rp++) {
            size_t r = rowBase + wm * 64 + mi * 16 + rp * 8 + (lane >> 2);
#pragma unroll
            for (int nj = 0; nj < 4; nj++) {
                int cgl = colBase + wn * 32 + nj * 8 + (lane & 3) * 2;
                epi.store(r, cgl, make_float2(acc[mi][nj][rp * 2],
                                              acc[mi][nj][rp * 2 + 1]));
            }
        }
}

// =================================================================
// FC2 GEMM (K=512, BK=32, 4-stage cp.async) + bias + ls2 + residual
// + TRANSPOSED store to d_out (B,C,P).
// =================================================================
__global__ __launch_bounds__(256, 2) void bgemm_fc2_tr_kernel(
    const __nv_bfloat16* __restrict__ A, const __nv_bfloat16* __restrict__ Bw,
    const float* __restrict__ bias, const float* __restrict__ ls,
    const float* __restrict__ resid, float* __restrict__ out)
{
    __shared__ __align__(16) __nv_bfloat16 As[4][128][LDS_S];
    __shared__ __align__(16) __nv_bfloat16 Bs[4][128][LDS_S];
    __shared__ float tsm[32][132];
    constexpr int K = 512;
    constexpr int S = K >> 5;
    int tid = threadIdx.x, lane = tid & 31, w = tid >> 5;
    int wm = w & 1, wn = w >> 1;
    size_t rowBase = (size_t)blockIdx.y * 128;

    int ldRow = tid >> 1, ldHalf = tid & 1;
    u32 sAbase = (u32)__cvta_generic_to_shared(&As[0][0][0]);
    u32 sBbase = (u32)__cvta_generic_to_shared(&Bs[0][0][0]);
    constexpr u32 SLOT = 128 * LDS_S * 2;
    const __nv_bfloat16* Arow = A  + (rowBase + ldRow) * K + ldHalf * 16;
    const __nv_bfloat16* Brow = Bw + (size_t)ldRow * K + ldHalf * 16;
    u32 dstOff = (u32)((ldRow * LDS_S + ldHalf * 16) * 2);

    auto issue = [&](int t, int slot) {
        const __nv_bfloat16* sa = Arow + t * 32;
        const __nv_bfloat16* sb = Brow + t * 32;
        u32 da = sAbase + slot * SLOT + dstOff;
        u32 db = sBbase + slot * SLOT + dstOff;
        cp16(da, sa); cp16(da + 16, sa + 8);
        cp16(db, sb); cp16(db + 16, sb + 8);
    };

    issue(0, 0); cp_commit();
    issue(1, 1); cp_commit();
    issue(2, 2); cp_commit();

    float acc[4][4][4];
#pragma unroll
    for (int i = 0; i < 4; i++)
#pragma unroll
        for (int j = 0; j < 4; j++)
#pragma unroll
            for (int r = 0; r < 4; r++) acc[i][j][r] = 0.f;

    int arow = wm * 64 + (lane & 15);
    int brow = wn * 32 + (lane & 15);
    int csel = (lane >> 4) * 8;

    for (int t = 0; t < S; t++) {
        cp_wait<2>();
        __syncthreads();
        if (t + 3 < S) issue(t + 3, (t + 3) & 3);
        cp_commit();

        u32 sA = sAbase + (u32)((t & 3) * SLOT);
        u32 sB = sBbase + (u32)((t & 3) * SLOT);
#pragma unroll
        for (int kk = 0; kk < 32; kk += 16) {
            u32 af[4][4], bf[4][2];
            int acol = kk + csel;
#pragma unroll
            for (int mi = 0; mi < 4; mi++) {
                u32 addr = sA + (u32)(((arow + mi * 16) * LDS_S + acol) * 2);
                ldsm_x4(af[mi][0], af[mi][1], af[mi][2], af[mi][3], addr);
            }
#pragma unroll
            for (int np = 0; np < 2; np++) {
                u32 r0, r1, r2, r3;
                u32 addr = sB + (u32)(((brow + np * 16) * LDS_S + acol) * 2);
                ldsm_x4(r0, r1, r2, r3, addr);
                bf[np * 2][0]     = r0; bf[np * 2][1]     = r2;
                bf[np * 2 + 1][0] = r1; bf[np * 2 + 1][1] = r3;
            }
#pragma unroll
            for (int mi = 0; mi < 4; mi++)
#pragma unroll
                for (int nj = 0; nj < 4; nj++)
                    mma_bf16(acc[mi][nj], af[mi], bf[nj]);
        }
    }

    // epilogue: bias + ls + residual, transposed write
    int b  = (int)(rowBase / P);
    int p0 = (int)(rowBase % P);
#pragma unroll
    for (int cg = 0; cg < 4; cg++) {
        __syncthreads();
        if (wn == cg) {
#pragma unroll
            for (int mi = 0; mi < 4; mi++)
#pragma unroll
                for (int rp = 0; rp < 2; rp++) {
                    int pl = wm * 64 + mi * 16 + rp * 8 + (lane >> 2);
                    size_t grow = rowBase + pl;
#pragma unroll
                    for (int nj = 0; nj < 4; nj++) {
                        int cl = nj * 8 + (lane & 3) * 2;
                        int cglob = cg * 32 + cl;
                        float2 bb = *(const float2*)(bias + cglob);
                        float2 ss = *(const float2*)(ls + cglob);
                        float2 rr = *(const float2*)(resid + grow * 128 + cglob);
                        tsm[cl][pl]     = rr.x + ss.x * (acc[mi][nj][rp*2]   + bb.x);
                        tsm[cl + 1][pl] = rr.y + ss.y * (acc[mi][nj][rp*2+1] + bb.y);
                    }
                }
        }
        __syncthreads();
        int c  = tid >> 3;
        int pj = (tid & 7) * 16;
        float* dst = out + (size_t)b * C * P + (size_t)(cg * 32 + c) * P + p0 + pj;
        const float* srcp = &tsm[c][pj];
#pragma unroll
        for (int j = 0; j < 4; j++)
            *(float4*)(dst + j * 4) = *(const float4*)(srcp + j * 4);
    }
}

// =================================================================
// Warp-level attention core
// =================================================================
constexpr int AST = 24;

__device__ __forceinline__ void attn_warp(
    const __nv_bfloat16* Qs, const __nv_bfloat16* Ks, const __nv_bfloat16* Vs,
    int nchunks, int lane, float o[2][2][4], float rsum[2][2])
{
    const float scale = 0.25f;
    int g = lane >> 3, i = lane & 7;
    int r4 = lane >> 2, c4 = lane & 3;

    u32 aq[2][4];
#pragma unroll
    for (int mt = 0; mt < 2; mt++) {
        u32 addr = (u32)__cvta_generic_to_shared(
            Qs + (mt * 16 + (g & 1) * 8 + i) * AST + (g >> 1) * 8);
        ldsm_x4(aq[mt][0], aq[mt][1], aq[mt][2], aq[mt][3], addr);
    }

#pragma unroll
    for (int mt = 0; mt < 2; mt++)
#pragma unroll
        for (int nh = 0; nh < 2; nh++)
#pragma unroll
            for (int q = 0; q < 4; q++) o[mt][nh][q] = 0.f;
    rsum[0][0] = rsum[0][1] = rsum[1][0] = rsum[1][1] = 0.f;

    for (int ch = 0; ch < nchunks; ch++) {
        const __nv_bfloat16* Kc = Ks + ch * 64 * AST;
        const __nv_bfloat16* Vc = Vs + ch * 64 * AST;
        u32 pf[2][4][4];
#pragma unroll
        for (int nt = 0; nt < 8; nt++) {
            const __nv_bfloat16* kp = Kc + (nt * 8 + r4) * AST + c4 * 2;
            u32 bb[2];
            bb[0] = *(const u32*)kp;
            bb[1] = *(const u32*)(kp + 8);
            float s0[4] = {0.f, 0.f, 0.f, 0.f};
            float s1[4] = {0.f, 0.f, 0.f, 0.f};
            mma_bf16(s0, aq[0], bb);
            mma_bf16(s1, aq[1], bb);
            float e00 = __expf(s0[0] * scale), e01 = __expf(s0[1] * scale);
            float e02 = __expf(s0[2] * scale), e03 = __expf(s0[3] * scale);
            float e10 = __expf(s1[0] * scale), e11 = __expf(s1[1] * scale);
            float e12 = __expf(s1[2] * scale), e13 = __expf(s1[3] * scale);
            rsum[0][0] += e00 + e01;  rsum[0][1] += e02 + e03;
            rsum[1][0] += e10 + e11;  rsum[1][1] += e12 + e13;
            int kt = nt >> 1, lo = (nt & 1) * 2;
            pf[0][kt][lo + 0] = pack_bf16x2(e00, e01);
            pf[0][kt][lo + 1] = pack_bf16x2(e02, e03);
            pf[1][kt][lo + 0] = pack_bf16x2(e10, e11);
            pf[1][kt][lo + 1] = pack_bf16x2(e12, e13);
        }
#pragma unroll
        for (int kt = 0; kt < 4; kt++) {
            u32 v0, v1, v2, v3;
            u32 addr = (u32)__cvta_generic_to_shared(
                Vc + (kt * 16 + (g & 1) * 8 + i) * AST + (g >> 1) * 8);
            ldsm_x4_t(v0, v1, v2, v3, addr);
            u32 b0[2] = {v0, v1};
            u32 b1[2] = {v2, v3};
            mma_bf16(o[0][0], pf[0][kt], b0);
            mma_bf16(o[0][1], pf[0][kt], b1);
            mma_bf16(o[1][0], pf[1][kt], b0);
            mma_bf16(o[1][1], pf[1][kt], b1);
        }
    }

#pragma unroll
    for (int mt = 0; mt < 2; mt++)
#pragma unroll
        for (int hh = 0; hh < 2; hh++) {
            float v = rsum[mt][hh];
            v += __shfl_xor_sync(0xffffffffu, v, 1);
            v += __shfl_xor_sync(0xffffffffu, v, 2);
            rsum[mt][hh] = v;
        }
}

// =================================================================
// Merged attention: blk<2048 window, else grid. 256 thr.
// =================================================================
__global__ __launch_bounds__(256) void attn_kernel(
    const __nv_bfloat16* __restrict__ qkv, __nv_bfloat16* __restrict__ abuf)
{
    __shared__ __align__(16) __nv_bfloat16 Qs[256 * AST];
    __shared__ __align__(16) __nv_bfloat16 Ks[256 * AST];
    __shared__ __align__(16) __nv_bfloat16 Vs[256 * AST];

    int blk = blockIdx.x;
    int tid = threadIdx.x;
    int wrp = tid >> 5, lane = tid & 31;
    int r4 = lane >> 2, c4 = lane & 3;

    if (blk < 2048) {
        // ---- window attention: (b, wy, wx); 4 heads x 2 warps ----
        int b  = blk >> 8;
        int wy = (blk >> 4) & 15;
        int wx = blk & 15;
        {
            int h = tid >> 6, t = tid & 63;
            int y = t >> 3, x = t & 7;
            size_t p = (size_t)(wy * 8 + y) * WW + wx * 8 + x;
            const __nv_bfloat16* base = qkv + ((size_t)b * P + p) * 384 + h * 16;
            int row = (h * 64 + t) * AST;
            const uint4* q4 = (const uint4*)base;
            const uint4* k4 = (const uint4*)(base + 128);
            const uint4* v4 = (const uint4*)(base + 256);
            *(uint4*)&Qs[row] = q4[0];  *(uint4*)&Qs[row + 8] = q4[1];
            *(uint4*)&Ks[row] = k4[0];  *(uint4*)&Ks[row + 8] = k4[1];
            *(uint4*)&Vs[row] = v4[0];  *(uint4*)&Vs[row + 8] = v4[1];
        }
        __syncthreads();

        int h = wrp >> 1;
        int qb = (wrp & 1) * 32;
        float o[2][2][4], rsum[2][2];
        attn_warp(Qs + (h * 64 + qb) * AST, Ks + h * 64 * AST, Vs + h * 64 * AST,
                  1, lane, o, rsum);

#pragma unroll
        for (int mt = 0; mt < 2; mt++) {
            float inv0 = 1.f / rsum[mt][0];
            float inv1 = 1.f / rsum[mt][1];
#pragma unroll
            for (int hh = 0; hh < 2; hh++) {
                int q = qb + mt * 16 + hh * 8 + r4;
                size_t p = (size_t)(wy * 8 + (q >> 3)) * WW + wx * 8 + (q & 7);
                float inv = hh ? inv1 : inv0;
                __nv_bfloat16* ob = abuf + ((size_t)b * P + p) * C + h * 16;
#pragma unroll
                for (int nh = 0; nh < 2; nh++) {
                    float ox = o[mt][nh][hh * 2]     * inv;
                    float oy = o[mt][nh][hh * 2 + 1] * inv;
                    *(__nv_bfloat162*)(ob + nh * 8 + c4 * 2) =
                        __floats2bfloat162_rn(ox, oy);
                }
            }
        }
    } else {
        // ---- grid attention: (b, pos, head); 8 warps x 32 q ----
        int gb  = blk - 2048;
        int b   = gb >> 8;
        int pos = (gb >> 2) & 63;
        int hg  = gb & 3;
        int y = pos >> 3, x = pos & 7;
        {
            int j = tid;
            int wy = j >> 4, wx = j & 15;
            size_t p = (size_t)(wy * 8 + y) * WW + wx * 8 + x;
            const __nv_bfloat16* base = qkv + ((size_t)b * P + p) * 384 + 64 + hg * 16;
            int row = j * AST;
            const uint4* q4 = (const uint4*)base;
            const uint4* k4 = (const uint4*)(base + 128);
            const uint4* v4 = (const uint4*)(base + 256);
            *(uint4*)&Qs[row] = q4[0];  *(uint4*)&Qs[row + 8] = q4[1];
            *(uint4*)&Ks[row] = k4[0];  *(uint4*)&Ks[row + 8] = k4[1];
            *(uint4*)&Vs[row] = v4[0];  *(uint4*)&Vs[row + 8] = v4[1];
        }
        __syncthreads();

        int qb = wrp * 32;
        float o[2][2][4], rsum[2][2];
        attn_warp(Qs + qb * AST, Ks, Vs, 4, lane, o, rsum);

#pragma unroll
        for (int mt = 0; mt < 2; mt++) {
            float inv0 = 1.f / rsum[mt][0];
            float inv1 = 1.f / rsum[mt][1];
#pragma unroll
            for (int hh = 0; hh < 2; hh++) {
                int j = qb + mt * 16 + hh * 8 + r4;
                int wy = j >> 4, wx = j & 15;
                size_t p = (size_t)(wy * 8 + y) * WW + wx * 8 + x;
                float inv = hh ? inv1 : inv0;
                __nv_bfloat16* ob = abuf + ((size_t)b * P + p) * C + 64 + hg * 16;
#pragma unroll
                for (int nh = 0; nh < 2; nh++) {
                    float ox = o[mt][nh][hh * 2]     * inv;
                    float oy = o[mt][nh][hh * 2 + 1] * inv;
                    *(__nv_bfloat162*)(ob + nh * 8 + c4 * 2) =
                        __floats2bfloat162_rn(ox, oy);
                }
            }
        }
    }
}

// =================================================================
// host launcher
// =================================================================
extern "C" void kernel_launch(void* const* d_in, const int* in_sizes, int n_in,
                              void* d_out, int out_size)
{
    const float* x       = (const float*)d_in[0];
    const float* conv_w  = (const float*)d_in[1];
    const float* conv_b  = (const float*)d_in[2];
    const float* norm1_w = (const float*)d_in[3];
    const float* norm1_b = (const float*)d_in[4];
    const float* wqkv    = (const float*)d_in[5];
    const float* proj_w  = (const float*)d_in[6];
    const float* proj_b  = (const float*)d_in[7];
    const float* norm2_w = (const float*)d_in[8];
    const float* norm2_b = (const float*)d_in[9];
    const float* fc1_w   = (const float*)d_in[10];
    const float* fc1_b   = (const float*)d_in[11];
    const float* fc2_w   = (const float*)d_in[12];
    const float* fc2_b   = (const float*)d_in[13];
    const float* ls1     = (const float*)d_in[14];
    const float* ls2     = (const float*)d_in[15];
    float* out = (float*)d_out;

    float *pxt, *pxt2;
    __nv_bfloat16 *pqkv, *pabuf, *ph, *pwq, *pwp, *pw1, *pw2;
    cudaGetSymbolAddress((void**)&pxt,   g_xt);
    cudaGetSymbolAddress((void**)&pqkv,  g_qkvb);
    cudaGetSymbolAddress((void**)&pabuf, g_abuf);
    cudaGetSymbolAddress((void**)&pxt2,  g_xt2);
    cudaGetSymbolAddress((void**)&ph,    g_h);
    cudaGetSymbolAddress((void**)&pwq,   g_wqkv_t);
    cudaGetSymbolAddress((void**)&pwp,   g_proj_t);
    cudaGetSymbolAddress((void**)&pw1,   g_fc1_t);
    cudaGetSymbolAddress((void**)&pw2,   g_fc2_t);

    // 0. weight prep
    wt_all_kernel<<<192, dim3(32, 8)>>>(wqkv, proj_w, fc1_w, fc2_w,
                                        pwq, pwp, pw1, pw2);

    // 1. conv + residual + transpose -> xt
    conv_kernel<<<dim3(16, HH, BS), 256>>>(x, conv_w, conv_b, pxt);

    // 2. LN1 + QKV GEMM fused
    {
        EpiQKVb e{pqkv};
        lngemm_kernel<3, EpiQKVb><<<(unsigned)(M / 128), 256>>>(
            pxt, norm1_w, norm1_b, pwq, e);
    }

    // 3. merged attention
    attn_kernel<<<2 * BS * 256, 256>>>(pqkv, pabuf);

    // 4. proj GEMM + ls1 + residual -> xt2
    {
        EpiProj e{proj_b, ls1, pxt, pxt2};
        bgemm_kernel<EpiProj><<<dim3(1, (unsigned)(M / 128)), 256>>>(pabuf, pwp, 128, e);
    }

    // 5. LN2 + FC1 GEMM fused
    {
        EpiGelu e{fc1_b, ph};
        lngemm_kernel<4, EpiGelu><<<(unsigned)(M / 128), 256>>>(
            pxt2, norm2_w, norm2_b, pw1, e);
    }

    // 6. FC2 + bias + ls2 + residual + transposed store -> d_out
    bgemm_fc2_tr_kernel<<<dim3(1, (unsigned)(M / 128)), 256>>>(
        ph, pw2, fc2_b, ls2, pxt2, out);

    (void)in_sizes; (void)n_in; (void)out_size;
}